// round 1
// baseline (speedup 1.0000x reference)
#include <cuda_runtime.h>
#include <cstdint>

#define N_NODES 100000
#define HID 128
#define IN_DIM 8

// ---------------- scratch (static __device__, no allocation) ----------------
__device__ float g_h1[(size_t)N_NODES * HID];
__device__ float g_h2[(size_t)N_NODES * HID];
__device__ float g_agg[(size_t)N_NODES * HID];
__device__ float g_agg8[(size_t)N_NODES * IN_DIM];
__device__ float g_inv_conn[N_NODES];
__device__ float g_inv_dest[N_NODES];

// ---------------- helpers ----------------
__device__ __forceinline__ void red4(float* p, float4 v) {
    asm volatile("red.global.add.v4.f32 [%0], {%1,%2,%3,%4};"
                 :: "l"(p), "f"(v.x), "f"(v.y), "f"(v.z), "f"(v.w) : "memory");
}

__global__ void zero_f(float* p, size_t n) {
    size_t i = (size_t)blockIdx.x * blockDim.x + threadIdx.x;
    size_t st = (size_t)gridDim.x * blockDim.x;
    for (; i < n; i += st) p[i] = 0.f;
}

// count in-degree for both edge lists in one pass
__global__ void count_kernel(const int* __restrict__ ei_c, const int* __restrict__ ei_d,
                             int E, float* cnt_c, float* cnt_d) {
    int i = blockIdx.x * blockDim.x + threadIdx.x;
    int st = gridDim.x * blockDim.x;
    for (; i < E; i += st) {
        atomicAdd(&cnt_c[ei_c[E + i]], 1.f);
        atomicAdd(&cnt_d[ei_d[E + i]], 1.f);
    }
}

__global__ void inv_kernel(float* a, float* b, int n) {
    int i = blockIdx.x * blockDim.x + threadIdx.x;
    if (i < n) {
        a[i] = 1.f / fmaxf(a[i], 1.f);
        b[i] = 1.f / fmaxf(b[i], 1.f);
    }
}

// ---------------- layer-1 aggregation (d=8): one thread per edge ----------------
__global__ void scatter8(const float* __restrict__ x, const int* __restrict__ ei,
                         int E, float* __restrict__ agg8) {
    int e = blockIdx.x * blockDim.x + threadIdx.x;
    if (e >= E) return;
    int s = ei[e];
    int d = ei[E + e];
    const float4* xr = (const float4*)(x + (size_t)s * IN_DIM);
    float4 a = xr[0], b = xr[1];
    float* dp = agg8 + (size_t)d * IN_DIM;
    red4(dp, a);
    red4(dp + 4, b);
}

// ---------------- layer-2/3 aggregation (d=128): one warp per edge ----------------
__global__ void scatter128(const float* __restrict__ h, const int* __restrict__ ei,
                           int E, float* __restrict__ agg) {
    int warp = (blockIdx.x * blockDim.x + threadIdx.x) >> 5;
    int lane = threadIdx.x & 31;
    if (warp >= E) return;
    int s = __ldg(ei + warp);
    int d = __ldg(ei + E + warp);
    float4 v = *(const float4*)(h + (size_t)s * HID + lane * 4);
    red4(agg + (size_t)d * HID + lane * 4, v);
}

// ---------------- layer 1: d_in=8 -> 128, one warp per node ----------------
__global__ void layer1_kernel(const float* __restrict__ x, const float* __restrict__ agg8,
                              const float* __restrict__ inv,
                              const float* __restrict__ wl, const float* __restrict__ wr,
                              const float* __restrict__ bias,
                              float* __restrict__ out, int n) {
    __shared__ float s_wl[IN_DIM * HID];
    __shared__ float s_wr[IN_DIM * HID];
    __shared__ float s_b[HID];
    for (int i = threadIdx.x; i < IN_DIM * HID; i += blockDim.x) {
        s_wl[i] = wl[i];
        s_wr[i] = wr[i];
    }
    if (threadIdx.x < HID) s_b[threadIdx.x] = bias[threadIdx.x];
    __syncthreads();

    int warp = threadIdx.x >> 5, lane = threadIdx.x & 31;
    int node = blockIdx.x * (blockDim.x >> 5) + warp;
    if (node >= n) return;

    // lanes 0-7: x row; lanes 8-15: agg row; lane 16: inv count
    float my = 0.f;
    if (lane < 8)       my = x[(size_t)node * IN_DIM + lane];
    else if (lane < 16) my = agg8[(size_t)node * IN_DIM + (lane - 8)];
    else if (lane == 16) my = inv[node];
    float iv = __shfl_sync(0xffffffffu, my, 16);
    float xs[8], as[8];
#pragma unroll
    for (int k = 0; k < 8; k++) {
        xs[k] = __shfl_sync(0xffffffffu, my, k);
        as[k] = __shfl_sync(0xffffffffu, my, 8 + k) * iv;
    }
    float acc[4];
#pragma unroll
    for (int c = 0; c < 4; c++) {
        int j = lane + 32 * c;
        float a = s_b[j];
#pragma unroll
        for (int k = 0; k < 8; k++)
            a += as[k] * s_wl[k * HID + j] + xs[k] * s_wr[k * HID + j];
        acc[c] = a;
    }
    float ss = acc[0] * acc[0] + acc[1] * acc[1] + acc[2] * acc[2] + acc[3] * acc[3];
#pragma unroll
    for (int o = 16; o >= 1; o >>= 1) ss += __shfl_xor_sync(0xffffffffu, ss, o);
    float invn = 1.f / fmaxf(sqrtf(ss), 1e-12f);
#pragma unroll
    for (int c = 0; c < 4; c++)
        out[(size_t)node * HID + lane + 32 * c] = tanhf(acc[c] * invn);
}

// ---------------- layers 2/3: fused [mean|h] @ [wl;wr] + b, l2norm, tanh ----------------
// M=n, N=128, K=256. BM=128, BN=128, BK=16, 256 threads, 8x8 register tile.
#define BM 128
#define BN 128
#define BK 16

__global__ __launch_bounds__(256) void layer23_kernel(
    const float* __restrict__ hin, const float* __restrict__ agg,
    const float* __restrict__ inv,
    const float* __restrict__ wl, const float* __restrict__ wr,
    const float* __restrict__ bias, float* __restrict__ out, int n) {
    __shared__ float As[BK][BM + 4];
    __shared__ float Bs[BK][BN];

    int t = threadIdx.x;
    int row0 = blockIdx.x * BM;
    int tm = t >> 4;   // 0..15, row group (8 rows each)
    int tn = t & 15;   // 0..15, col group (cols tn*4..+3 and 64+tn*4..+3)

    float acc[8][8];
#pragma unroll
    for (int i = 0; i < 8; i++)
#pragma unroll
        for (int j = 0; j < 8; j++) acc[i][j] = 0.f;

    for (int kc = 0; kc < 256; kc += BK) {
        // --- stage A (2048 floats) and B (2048 floats), 2 float4 each per thread ---
#pragma unroll
        for (int r = 0; r < 2; r++) {
            int f = t + r * 256;
            // A: 16 floats (4 float4) per row
            int m = f >> 2, kq = f & 3;
            int gi = row0 + m;
            int ic = gi < n ? gi : n - 1;
            float4 v;
            if (kc < 128) {
                v = *(const float4*)(agg + (size_t)ic * HID + kc + kq * 4);
                float s = __ldg(inv + ic);
                v.x *= s; v.y *= s; v.z *= s; v.w *= s;
            } else {
                v = *(const float4*)(hin + (size_t)ic * HID + (kc - 128) + kq * 4);
            }
            As[kq * 4 + 0][m] = v.x;
            As[kq * 4 + 1][m] = v.y;
            As[kq * 4 + 2][m] = v.z;
            As[kq * 4 + 3][m] = v.w;
            // B: 128 floats (32 float4) per row
            int kb = f >> 5, q = f & 31;
            int kg = kc + kb;
            const float* wsrc = (kg < 128) ? (wl + (size_t)kg * HID)
                                           : (wr + (size_t)(kg - 128) * HID);
            *(float4*)&Bs[kb][q * 4] = *(const float4*)(wsrc + q * 4);
        }
        __syncthreads();

#pragma unroll
        for (int kk = 0; kk < BK; kk++) {
            float a[8], b[8];
            *(float4*)&a[0] = *(const float4*)&As[kk][tm * 8];
            *(float4*)&a[4] = *(const float4*)&As[kk][tm * 8 + 4];
            *(float4*)&b[0] = *(const float4*)&Bs[kk][tn * 4];
            *(float4*)&b[4] = *(const float4*)&Bs[kk][64 + tn * 4];
#pragma unroll
            for (int i = 0; i < 8; i++)
#pragma unroll
                for (int j = 0; j < 8; j++) acc[i][j] += a[i] * b[j];
        }
        __syncthreads();
    }

    // --- epilogue: +bias, row L2 norm (reduce across 16 tn lanes), tanh ---
    float bv[8];
    *(float4*)&bv[0] = *(const float4*)(bias + tn * 4);
    *(float4*)&bv[4] = *(const float4*)(bias + 64 + tn * 4);

#pragma unroll
    for (int i = 0; i < 8; i++) {
        float ss = 0.f;
#pragma unroll
        for (int j = 0; j < 8; j++) {
            acc[i][j] += bv[j];
            ss += acc[i][j] * acc[i][j];
        }
        // threads sharing a row are the 16 consecutive lanes with same tm
#pragma unroll
        for (int o = 1; o < 16; o <<= 1) ss += __shfl_xor_sync(0xffffffffu, ss, o);
        float invn = 1.f / fmaxf(sqrtf(ss), 1e-12f);
        int gi = row0 + tm * 8 + i;
        if (gi < n) {
            float4 o1 = make_float4(tanhf(acc[i][0] * invn), tanhf(acc[i][1] * invn),
                                    tanhf(acc[i][2] * invn), tanhf(acc[i][3] * invn));
            float4 o2 = make_float4(tanhf(acc[i][4] * invn), tanhf(acc[i][5] * invn),
                                    tanhf(acc[i][6] * invn), tanhf(acc[i][7] * invn));
            *(float4*)(out + (size_t)gi * HID + tn * 4) = o1;
            *(float4*)(out + (size_t)gi * HID + 64 + tn * 4) = o2;
        }
    }
}

// ---------------- launch ----------------
extern "C" void kernel_launch(void* const* d_in, const int* in_sizes, int n_in,
                              void* d_out, int out_size) {
    const float* x       = (const float*)d_in[0];
    const int*   ei_conn = (const int*)d_in[1];
    const int*   ei_dest = (const int*)d_in[2];
    const float* w_l1 = (const float*)d_in[3];
    const float* w_r1 = (const float*)d_in[4];
    const float* b1   = (const float*)d_in[5];
    const float* w_l2 = (const float*)d_in[6];
    const float* w_r2 = (const float*)d_in[7];
    const float* b2   = (const float*)d_in[8];
    const float* w_l3 = (const float*)d_in[9];
    const float* w_r3 = (const float*)d_in[10];
    const float* b3   = (const float*)d_in[11];
    float* out = (float*)d_out;

    const int n = N_NODES;
    const int E = in_sizes[1] / 2;

    float *p_h1, *p_h2, *p_agg, *p_agg8, *p_invc, *p_invd;
    cudaGetSymbolAddress((void**)&p_h1, g_h1);
    cudaGetSymbolAddress((void**)&p_h2, g_h2);
    cudaGetSymbolAddress((void**)&p_agg, g_agg);
    cudaGetSymbolAddress((void**)&p_agg8, g_agg8);
    cudaGetSymbolAddress((void**)&p_invc, g_inv_conn);
    cudaGetSymbolAddress((void**)&p_invd, g_inv_dest);

    const int ZB = 1024;  // blocks for zero kernels

    // counts -> inverse counts
    zero_f<<<ZB, 256>>>(p_invc, n);
    zero_f<<<ZB, 256>>>(p_invd, n);
    count_kernel<<<2048, 256>>>(ei_conn, ei_dest, E, p_invc, p_invd);
    inv_kernel<<<(n + 255) / 256, 256>>>(p_invc, p_invd, n);

    // ---- layer 1 (ei_conn, d=8) ----
    zero_f<<<ZB, 256>>>(p_agg8, (size_t)n * IN_DIM);
    scatter8<<<(E + 255) / 256, 256>>>(x, ei_conn, E, p_agg8);
    layer1_kernel<<<(n + 7) / 8, 256>>>(x, p_agg8, p_invc, w_l1, w_r1, b1, p_h1, n);

    // ---- layer 2 (ei_dest, d=128) ----
    zero_f<<<ZB, 256>>>(p_agg, (size_t)n * HID);
    scatter128<<<(E * 32 + 255) / 256, 256>>>(p_h1, ei_dest, E, p_agg);
    layer23_kernel<<<(n + BM - 1) / BM, 256>>>(p_h1, p_agg, p_invd, w_l2, w_r2, b2, p_h2, n);

    // ---- layer 3 (ei_conn, d=128) ----
    zero_f<<<ZB, 256>>>(p_agg, (size_t)n * HID);
    scatter128<<<(E * 32 + 255) / 256, 256>>>(p_h2, ei_conn, E, p_agg);
    layer23_kernel<<<(n + BM - 1) / BM, 256>>>(p_h2, p_agg, p_invc, w_l3, w_r3, b3, out, n);
}

// round 2
// speedup vs baseline: 1.1924x; 1.1924x over previous
#include <cuda_runtime.h>
#include <cstdint>

#define N_NODES 100000
#define N_EDGES 1600000
#define HID 128
#define IN_DIM 8

// ---------------- scratch (static __device__, no allocation) ----------------
__device__ float g_h1[(size_t)N_NODES * HID];
__device__ float g_h2[(size_t)N_NODES * HID];
__device__ float g_agg[(size_t)N_NODES * HID];     // holds MEAN rows
__device__ float g_agg8[(size_t)N_NODES * IN_DIM]; // layer-1 mean
__device__ int g_cnt_c[N_NODES];
__device__ int g_cnt_d[N_NODES];
__device__ int g_rp_c[N_NODES + 1];
__device__ int g_rp_d[N_NODES + 1];
__device__ int g_cur_c[N_NODES];
__device__ int g_cur_d[N_NODES];
__device__ int g_src_c[N_EDGES];
__device__ int g_src_d[N_EDGES];

// ---------------- small utility kernels ----------------
__global__ void zero_u32_2(int* a, int* b, int n) {
    int i = blockIdx.x * blockDim.x + threadIdx.x;
    int st = gridDim.x * blockDim.x;
    for (; i < n; i += st) { a[i] = 0; b[i] = 0; }
}

// histogram of dst for both edge lists
__global__ void hist_kernel(const int* __restrict__ eic, const int* __restrict__ eid,
                            int E, int* cc, int* cd) {
    int i = blockIdx.x * blockDim.x + threadIdx.x;
    int st = gridDim.x * blockDim.x;
    for (; i < E; i += st) {
        atomicAdd(&cc[eic[E + i]], 1);
        atomicAdd(&cd[eid[E + i]], 1);
    }
}

// exclusive scan of counts -> rowptr (+cursor copy). One 1024-thread block per list.
__global__ __launch_bounds__(1024) void scan2_kernel(
    const int* c0, int* rp0, int* cur0,
    const int* c1, int* rp1, int* cur1, int n) {
    const int* cnt = blockIdx.x ? c1 : c0;
    int* rp  = blockIdx.x ? rp1 : rp0;
    int* cur = blockIdx.x ? cur1 : cur0;
    __shared__ int s[1024];
    int t = threadIdx.x;
    int per = (n + 1023) / 1024;
    int beg = t * per;
    int end = min(beg + per, n);
    int sum = 0;
    for (int i = beg; i < end; i++) sum += cnt[i];
    s[t] = sum;
    __syncthreads();
    for (int off = 1; off < 1024; off <<= 1) {
        int v = (t >= off) ? s[t - off] : 0;
        __syncthreads();
        s[t] += v;
        __syncthreads();
    }
    int run = s[t] - sum;  // exclusive prefix
    for (int i = beg; i < end; i++) {
        rp[i] = run;
        cur[i] = run;
        run += cnt[i];
    }
    if (t == 1023) rp[n] = s[1023];
}

// fill sorted-by-dst src lists for both edge lists
__global__ void fill_kernel(const int* __restrict__ eic, const int* __restrict__ eid,
                            int E, int* curc, int* curd,
                            int* __restrict__ srcc, int* __restrict__ srcd) {
    int i = blockIdx.x * blockDim.x + threadIdx.x;
    int st = gridDim.x * blockDim.x;
    for (; i < E; i += st) {
        int s = eic[i], d = eic[E + i];
        int p = atomicAdd(&curc[d], 1);
        srcc[p] = s;
        s = eid[i]; d = eid[E + i];
        p = atomicAdd(&curd[d], 1);
        srcd[p] = s;
    }
}

// ---------------- pull-style gather-mean, d=128: one warp per node ----------------
__global__ void gather128(const float* __restrict__ h, const int* __restrict__ rp,
                          const int* __restrict__ src, float* __restrict__ out, int n) {
    int node = (blockIdx.x * blockDim.x + threadIdx.x) >> 5;
    int lane = threadIdx.x & 31;
    if (node >= n) return;
    int b = __ldg(rp + node), e = __ldg(rp + node + 1);
    float4 acc = make_float4(0.f, 0.f, 0.f, 0.f);
    int j = b;
    for (; j + 4 <= e; j += 4) {
        int s0 = __ldg(src + j), s1 = __ldg(src + j + 1);
        int s2 = __ldg(src + j + 2), s3 = __ldg(src + j + 3);
        float4 v0 = *(const float4*)(h + (size_t)s0 * HID + lane * 4);
        float4 v1 = *(const float4*)(h + (size_t)s1 * HID + lane * 4);
        float4 v2 = *(const float4*)(h + (size_t)s2 * HID + lane * 4);
        float4 v3 = *(const float4*)(h + (size_t)s3 * HID + lane * 4);
        acc.x += (v0.x + v1.x) + (v2.x + v3.x);
        acc.y += (v0.y + v1.y) + (v2.y + v3.y);
        acc.z += (v0.z + v1.z) + (v2.z + v3.z);
        acc.w += (v0.w + v1.w) + (v2.w + v3.w);
    }
    for (; j < e; j++) {
        int s0 = __ldg(src + j);
        float4 v0 = *(const float4*)(h + (size_t)s0 * HID + lane * 4);
        acc.x += v0.x; acc.y += v0.y; acc.z += v0.z; acc.w += v0.w;
    }
    float inv = 1.f / fmaxf((float)(e - b), 1.f);
    acc.x *= inv; acc.y *= inv; acc.z *= inv; acc.w *= inv;
    *(float4*)(out + (size_t)node * HID + lane * 4) = acc;
}

// ---------------- gather-mean, d=8: 4 nodes per warp (8 lanes each) ----------------
__global__ void gather8(const float* __restrict__ x, const int* __restrict__ rp,
                        const int* __restrict__ src, float* __restrict__ out, int n) {
    int warp = (blockIdx.x * blockDim.x + threadIdx.x) >> 5;
    int lane = threadIdx.x & 31;
    int node = warp * 4 + (lane >> 3);
    int dim = lane & 7;
    if (node >= n) return;
    int b = __ldg(rp + node), e = __ldg(rp + node + 1);
    float acc = 0.f;
    int j = b;
    for (; j + 2 <= e; j += 2) {
        int s0 = __ldg(src + j), s1 = __ldg(src + j + 1);
        acc += __ldg(x + (size_t)s0 * IN_DIM + dim) + __ldg(x + (size_t)s1 * IN_DIM + dim);
    }
    if (j < e) acc += __ldg(x + (size_t)__ldg(src + j) * IN_DIM + dim);
    out[(size_t)node * IN_DIM + dim] = acc / fmaxf((float)(e - b), 1.f);
}

// ---------------- layer 1: d_in=8 -> 128, one warp per node ----------------
__global__ void layer1_kernel(const float* __restrict__ x, const float* __restrict__ mean8,
                              const float* __restrict__ wl, const float* __restrict__ wr,
                              const float* __restrict__ bias,
                              float* __restrict__ out, int n) {
    __shared__ float s_wl[IN_DIM * HID];
    __shared__ float s_wr[IN_DIM * HID];
    __shared__ float s_b[HID];
    for (int i = threadIdx.x; i < IN_DIM * HID; i += blockDim.x) {
        s_wl[i] = wl[i];
        s_wr[i] = wr[i];
    }
    if (threadIdx.x < HID) s_b[threadIdx.x] = bias[threadIdx.x];
    __syncthreads();

    int warp = threadIdx.x >> 5, lane = threadIdx.x & 31;
    int node = blockIdx.x * (blockDim.x >> 5) + warp;
    if (node >= n) return;

    // lanes 0-7: x row; lanes 8-15: mean row
    float my = 0.f;
    if (lane < 8)       my = x[(size_t)node * IN_DIM + lane];
    else if (lane < 16) my = mean8[(size_t)node * IN_DIM + (lane - 8)];
    float xs[8], as[8];
#pragma unroll
    for (int k = 0; k < 8; k++) {
        xs[k] = __shfl_sync(0xffffffffu, my, k);
        as[k] = __shfl_sync(0xffffffffu, my, 8 + k);
    }
    float acc[4];
#pragma unroll
    for (int c = 0; c < 4; c++) {
        int j = lane + 32 * c;
        float a = s_b[j];
#pragma unroll
        for (int k = 0; k < 8; k++)
            a += as[k] * s_wl[k * HID + j] + xs[k] * s_wr[k * HID + j];
        acc[c] = a;
    }
    float ss = acc[0] * acc[0] + acc[1] * acc[1] + acc[2] * acc[2] + acc[3] * acc[3];
#pragma unroll
    for (int o = 16; o >= 1; o >>= 1) ss += __shfl_xor_sync(0xffffffffu, ss, o);
    float invn = 1.f / fmaxf(sqrtf(ss), 1e-12f);
#pragma unroll
    for (int c = 0; c < 4; c++)
        out[(size_t)node * HID + lane + 32 * c] = tanhf(acc[c] * invn);
}

// ---------------- layers 2/3: fused [mean|h] @ [wl;wr] + b, l2norm, tanh ----------------
#define BM 128
#define BN 128
#define BK 16

__global__ __launch_bounds__(256) void layer23_kernel(
    const float* __restrict__ hin, const float* __restrict__ mean,
    const float* __restrict__ wl, const float* __restrict__ wr,
    const float* __restrict__ bias, float* __restrict__ out, int n) {
    __shared__ float As[BK][BM + 4];
    __shared__ float Bs[BK][BN];

    int t = threadIdx.x;
    int row0 = blockIdx.x * BM;
    int tm = t >> 4;
    int tn = t & 15;

    float acc[8][8];
#pragma unroll
    for (int i = 0; i < 8; i++)
#pragma unroll
        for (int j = 0; j < 8; j++) acc[i][j] = 0.f;

    for (int kc = 0; kc < 256; kc += BK) {
#pragma unroll
        for (int r = 0; r < 2; r++) {
            int f = t + r * 256;
            int m = f >> 2, kq = f & 3;
            int gi = row0 + m;
            int ic = gi < n ? gi : n - 1;
            const float* asrc = (kc < 128)
                ? (mean + (size_t)ic * HID + kc + kq * 4)
                : (hin + (size_t)ic * HID + (kc - 128) + kq * 4);
            float4 v = *(const float4*)asrc;
            As[kq * 4 + 0][m] = v.x;
            As[kq * 4 + 1][m] = v.y;
            As[kq * 4 + 2][m] = v.z;
            As[kq * 4 + 3][m] = v.w;
            int kb = f >> 5, q = f & 31;
            int kg = kc + kb;
            const float* wsrc = (kg < 128) ? (wl + (size_t)kg * HID)
                                           : (wr + (size_t)(kg - 128) * HID);
            *(float4*)&Bs[kb][q * 4] = *(const float4*)(wsrc + q * 4);
        }
        __syncthreads();

#pragma unroll
        for (int kk = 0; kk < BK; kk++) {
            float a[8], b[8];
            *(float4*)&a[0] = *(const float4*)&As[kk][tm * 8];
            *(float4*)&a[4] = *(const float4*)&As[kk][tm * 8 + 4];
            *(float4*)&b[0] = *(const float4*)&Bs[kk][tn * 4];
            *(float4*)&b[4] = *(const float4*)&Bs[kk][64 + tn * 4];
#pragma unroll
            for (int i = 0; i < 8; i++)
#pragma unroll
                for (int j = 0; j < 8; j++) acc[i][j] += a[i] * b[j];
        }
        __syncthreads();
    }

    float bv[8];
    *(float4*)&bv[0] = *(const float4*)(bias + tn * 4);
    *(float4*)&bv[4] = *(const float4*)(bias + 64 + tn * 4);

#pragma unroll
    for (int i = 0; i < 8; i++) {
        float ss = 0.f;
#pragma unroll
        for (int j = 0; j < 8; j++) {
            acc[i][j] += bv[j];
            ss += acc[i][j] * acc[i][j];
        }
#pragma unroll
        for (int o = 1; o < 16; o <<= 1) ss += __shfl_xor_sync(0xffffffffu, ss, o);
        float invn = 1.f / fmaxf(sqrtf(ss), 1e-12f);
        int gi = row0 + tm * 8 + i;
        if (gi < n) {
            float4 o1 = make_float4(tanhf(acc[i][0] * invn), tanhf(acc[i][1] * invn),
                                    tanhf(acc[i][2] * invn), tanhf(acc[i][3] * invn));
            float4 o2 = make_float4(tanhf(acc[i][4] * invn), tanhf(acc[i][5] * invn),
                                    tanhf(acc[i][6] * invn), tanhf(acc[i][7] * invn));
            *(float4*)(out + (size_t)gi * HID + tn * 4) = o1;
            *(float4*)(out + (size_t)gi * HID + 64 + tn * 4) = o2;
        }
    }
}

// ---------------- launch ----------------
extern "C" void kernel_launch(void* const* d_in, const int* in_sizes, int n_in,
                              void* d_out, int out_size) {
    const float* x       = (const float*)d_in[0];
    const int*   ei_conn = (const int*)d_in[1];
    const int*   ei_dest = (const int*)d_in[2];
    const float* w_l1 = (const float*)d_in[3];
    const float* w_r1 = (const float*)d_in[4];
    const float* b1   = (const float*)d_in[5];
    const float* w_l2 = (const float*)d_in[6];
    const float* w_r2 = (const float*)d_in[7];
    const float* b2   = (const float*)d_in[8];
    const float* w_l3 = (const float*)d_in[9];
    const float* w_r3 = (const float*)d_in[10];
    const float* b3   = (const float*)d_in[11];
    float* out = (float*)d_out;

    const int n = N_NODES;
    const int E = in_sizes[1] / 2;

    float *p_h1, *p_h2, *p_agg, *p_agg8;
    int *p_cnt_c, *p_cnt_d, *p_rp_c, *p_rp_d, *p_cur_c, *p_cur_d, *p_src_c, *p_src_d;
    cudaGetSymbolAddress((void**)&p_h1, g_h1);
    cudaGetSymbolAddress((void**)&p_h2, g_h2);
    cudaGetSymbolAddress((void**)&p_agg, g_agg);
    cudaGetSymbolAddress((void**)&p_agg8, g_agg8);
    cudaGetSymbolAddress((void**)&p_cnt_c, g_cnt_c);
    cudaGetSymbolAddress((void**)&p_cnt_d, g_cnt_d);
    cudaGetSymbolAddress((void**)&p_rp_c, g_rp_c);
    cudaGetSymbolAddress((void**)&p_rp_d, g_rp_d);
    cudaGetSymbolAddress((void**)&p_cur_c, g_cur_c);
    cudaGetSymbolAddress((void**)&p_cur_d, g_cur_d);
    cudaGetSymbolAddress((void**)&p_src_c, g_src_c);
    cudaGetSymbolAddress((void**)&p_src_d, g_src_d);

    // ---- CSR build for both edge lists ----
    zero_u32_2<<<(n + 255) / 256, 256>>>(p_cnt_c, p_cnt_d, n);
    hist_kernel<<<2048, 256>>>(ei_conn, ei_dest, E, p_cnt_c, p_cnt_d);
    scan2_kernel<<<2, 1024>>>(p_cnt_c, p_rp_c, p_cur_c, p_cnt_d, p_rp_d, p_cur_d, n);
    fill_kernel<<<2048, 256>>>(ei_conn, ei_dest, E, p_cur_c, p_cur_d, p_src_c, p_src_d);

    // ---- layer 1 (conn, d=8) ----
    gather8<<<(n * 8 + 255) / 256, 256>>>(x, p_rp_c, p_src_c, p_agg8, n);
    layer1_kernel<<<(n + 7) / 8, 256>>>(x, p_agg8, w_l1, w_r1, b1, p_h1, n);

    // ---- layer 2 (dest, d=128) ----
    gather128<<<(n * 32 + 255) / 256, 256>>>(p_h1, p_rp_d, p_src_d, p_agg, n);
    layer23_kernel<<<(n + BM - 1) / BM, 256>>>(p_h1, p_agg, w_l2, w_r2, b2, p_h2, n);

    // ---- layer 3 (conn, d=128) ----
    gather128<<<(n * 32 + 255) / 256, 256>>>(p_h2, p_rp_c, p_src_c, p_agg, n);
    layer23_kernel<<<(n + BM - 1) / BM, 256>>>(p_h2, p_agg, w_l3, w_r3, b3, out, n);
}

// round 3
// speedup vs baseline: 1.2029x; 1.0088x over previous
#include <cuda_runtime.h>
#include <cstdint>

#define N_NODES 100000
#define N_EDGES 1600000
#define HID 128
#define IN_DIM 8

// ---------------- scratch (static __device__, no allocation) ----------------
__device__ float g_h1[(size_t)N_NODES * HID];
__device__ float g_h2[(size_t)N_NODES * HID];
__device__ float g_agg[(size_t)N_NODES * HID];     // holds MEAN rows
__device__ float g_agg8[(size_t)N_NODES * IN_DIM]; // layer-1 mean
__device__ int g_cnt_c[N_NODES];
__device__ int g_cnt_d[N_NODES];
__device__ int g_rp_c[N_NODES + 1];
__device__ int g_rp_d[N_NODES + 1];
__device__ int g_cur_c[N_NODES];
__device__ int g_cur_d[N_NODES];
__device__ int g_src_c[N_EDGES];
__device__ int g_src_d[N_EDGES];

// ---------------- small utility kernels ----------------
__global__ void zero_u32_2(int* a, int* b, int n) {
    int i = blockIdx.x * blockDim.x + threadIdx.x;
    int st = gridDim.x * blockDim.x;
    for (; i < n; i += st) { a[i] = 0; b[i] = 0; }
}

__global__ void hist_kernel(const int* __restrict__ eic, const int* __restrict__ eid,
                            int E, int* cc, int* cd) {
    int i = blockIdx.x * blockDim.x + threadIdx.x;
    int st = gridDim.x * blockDim.x;
    for (; i < E; i += st) {
        atomicAdd(&cc[eic[E + i]], 1);
        atomicAdd(&cd[eid[E + i]], 1);
    }
}

__global__ __launch_bounds__(1024) void scan2_kernel(
    const int* c0, int* rp0, int* cur0,
    const int* c1, int* rp1, int* cur1, int n) {
    const int* cnt = blockIdx.x ? c1 : c0;
    int* rp  = blockIdx.x ? rp1 : rp0;
    int* cur = blockIdx.x ? cur1 : cur0;
    __shared__ int s[1024];
    int t = threadIdx.x;
    int per = (n + 1023) / 1024;
    int beg = t * per;
    int end = min(beg + per, n);
    int sum = 0;
    for (int i = beg; i < end; i++) sum += cnt[i];
    s[t] = sum;
    __syncthreads();
    for (int off = 1; off < 1024; off <<= 1) {
        int v = (t >= off) ? s[t - off] : 0;
        __syncthreads();
        s[t] += v;
        __syncthreads();
    }
    int run = s[t] - sum;
    for (int i = beg; i < end; i++) {
        rp[i] = run;
        cur[i] = run;
        run += cnt[i];
    }
    if (t == 1023) rp[n] = s[1023];
}

__global__ void fill_kernel(const int* __restrict__ eic, const int* __restrict__ eid,
                            int E, int* curc, int* curd,
                            int* __restrict__ srcc, int* __restrict__ srcd) {
    int i = blockIdx.x * blockDim.x + threadIdx.x;
    int st = gridDim.x * blockDim.x;
    for (; i < E; i += st) {
        int s = eic[i], d = eic[E + i];
        int p = atomicAdd(&curc[d], 1);
        srcc[p] = s;
        s = eid[i]; d = eid[E + i];
        p = atomicAdd(&curd[d], 1);
        srcd[p] = s;
    }
}

// ---------------- pull-style gather-mean, d=128: one warp per node ----------------
__global__ void gather128(const float* __restrict__ h, const int* __restrict__ rp,
                          const int* __restrict__ src, float* __restrict__ out, int n) {
    int node = (blockIdx.x * blockDim.x + threadIdx.x) >> 5;
    int lane = threadIdx.x & 31;
    if (node >= n) return;
    int b = __ldg(rp + node), e = __ldg(rp + node + 1);
    float4 acc = make_float4(0.f, 0.f, 0.f, 0.f);
    int j = b;
    for (; j + 4 <= e; j += 4) {
        int s0 = __ldg(src + j), s1 = __ldg(src + j + 1);
        int s2 = __ldg(src + j + 2), s3 = __ldg(src + j + 3);
        float4 v0 = *(const float4*)(h + (size_t)s0 * HID + lane * 4);
        float4 v1 = *(const float4*)(h + (size_t)s1 * HID + lane * 4);
        float4 v2 = *(const float4*)(h + (size_t)s2 * HID + lane * 4);
        float4 v3 = *(const float4*)(h + (size_t)s3 * HID + lane * 4);
        acc.x += (v0.x + v1.x) + (v2.x + v3.x);
        acc.y += (v0.y + v1.y) + (v2.y + v3.y);
        acc.z += (v0.z + v1.z) + (v2.z + v3.z);
        acc.w += (v0.w + v1.w) + (v2.w + v3.w);
    }
    for (; j < e; j++) {
        int s0 = __ldg(src + j);
        float4 v0 = *(const float4*)(h + (size_t)s0 * HID + lane * 4);
        acc.x += v0.x; acc.y += v0.y; acc.z += v0.z; acc.w += v0.w;
    }
    float inv = 1.f / fmaxf((float)(e - b), 1.f);
    acc.x *= inv; acc.y *= inv; acc.z *= inv; acc.w *= inv;
    *(float4*)(out + (size_t)node * HID + lane * 4) = acc;
}

// ---------------- gather-mean, d=8: 4 nodes per warp ----------------
__global__ void gather8(const float* __restrict__ x, const int* __restrict__ rp,
                        const int* __restrict__ src, float* __restrict__ out, int n) {
    int warp = (blockIdx.x * blockDim.x + threadIdx.x) >> 5;
    int lane = threadIdx.x & 31;
    int node = warp * 4 + (lane >> 3);
    int dim = lane & 7;
    if (node >= n) return;
    int b = __ldg(rp + node), e = __ldg(rp + node + 1);
    float acc = 0.f;
    int j = b;
    for (; j + 2 <= e; j += 2) {
        int s0 = __ldg(src + j), s1 = __ldg(src + j + 1);
        acc += __ldg(x + (size_t)s0 * IN_DIM + dim) + __ldg(x + (size_t)s1 * IN_DIM + dim);
    }
    if (j < e) acc += __ldg(x + (size_t)__ldg(src + j) * IN_DIM + dim);
    out[(size_t)node * IN_DIM + dim] = acc / fmaxf((float)(e - b), 1.f);
}

// ---------------- layer 1: d_in=8 -> 128, one warp per node ----------------
__global__ void layer1_kernel(const float* __restrict__ x, const float* __restrict__ mean8,
                              const float* __restrict__ wl, const float* __restrict__ wr,
                              const float* __restrict__ bias,
                              float* __restrict__ out, int n) {
    __shared__ float s_wl[IN_DIM * HID];
    __shared__ float s_wr[IN_DIM * HID];
    __shared__ float s_b[HID];
    for (int i = threadIdx.x; i < IN_DIM * HID; i += blockDim.x) {
        s_wl[i] = wl[i];
        s_wr[i] = wr[i];
    }
    if (threadIdx.x < HID) s_b[threadIdx.x] = bias[threadIdx.x];
    __syncthreads();

    int warp = threadIdx.x >> 5, lane = threadIdx.x & 31;
    int node = blockIdx.x * (blockDim.x >> 5) + warp;
    if (node >= n) return;

    float my = 0.f;
    if (lane < 8)       my = x[(size_t)node * IN_DIM + lane];
    else if (lane < 16) my = mean8[(size_t)node * IN_DIM + (lane - 8)];
    float xs[8], as[8];
#pragma unroll
    for (int k = 0; k < 8; k++) {
        xs[k] = __shfl_sync(0xffffffffu, my, k);
        as[k] = __shfl_sync(0xffffffffu, my, 8 + k);
    }
    float acc[4];
#pragma unroll
    for (int c = 0; c < 4; c++) {
        int j = lane + 32 * c;
        float a = s_b[j];
#pragma unroll
        for (int k = 0; k < 8; k++)
            a += as[k] * s_wl[k * HID + j] + xs[k] * s_wr[k * HID + j];
        acc[c] = a;
    }
    float ss = acc[0] * acc[0] + acc[1] * acc[1] + acc[2] * acc[2] + acc[3] * acc[3];
#pragma unroll
    for (int o = 16; o >= 1; o >>= 1) ss += __shfl_xor_sync(0xffffffffu, ss, o);
    float invn = 1.f / fmaxf(sqrtf(ss), 1e-12f);
#pragma unroll
    for (int c = 0; c < 4; c++)
        out[(size_t)node * HID + lane + 32 * c] = tanhf(acc[c] * invn);
}

// ---------------- tf32 tensor-core GEMM, layers 2/3 ----------------
// out[M,128] = tanh(l2norm([mean|hin] @ [wl;wr] + b)); 3-term tf32 split.
#define BM 128
#define BN 128
#define BK 32
#define LDP 132  // padded minor stride

__device__ __forceinline__ uint32_t f2tf(float v) {
    uint32_t r;
    asm("cvt.rna.tf32.f32 %0, %1;" : "=r"(r) : "f"(v));
    return r;
}

__device__ __forceinline__ void mma_tf32(float* c, uint32_t a0, uint32_t a1,
                                         uint32_t a2, uint32_t a3,
                                         uint32_t b0, uint32_t b1) {
    asm volatile(
        "mma.sync.aligned.m16n8k8.row.col.f32.tf32.tf32.f32 "
        "{%0,%1,%2,%3}, {%4,%5,%6,%7}, {%8,%9}, {%0,%1,%2,%3};"
        : "+f"(c[0]), "+f"(c[1]), "+f"(c[2]), "+f"(c[3])
        : "r"(a0), "r"(a1), "r"(a2), "r"(a3), "r"(b0), "r"(b1));
}

extern __shared__ uint32_t s_raw[];

__global__ __launch_bounds__(256, 2) void layer23_tc(
    const float* __restrict__ hin, const float* __restrict__ mean,
    const float* __restrict__ wl, const float* __restrict__ wr,
    const float* __restrict__ bias, float* __restrict__ out, int n) {
    uint32_t* As_hi = s_raw;                 // [BK][LDP]
    uint32_t* As_lo = As_hi + BK * LDP;
    uint32_t* Bs_hi = As_lo + BK * LDP;
    uint32_t* Bs_lo = Bs_hi + BK * LDP;
    float* ss_part = (float*)(Bs_lo + BK * LDP);  // [2][BM]

    int t = threadIdx.x;
    int row0 = blockIdx.x * BM;
    int wid = t >> 5, lane = t & 31;
    int warp_m = wid & 3;          // 4 warps over M (32 rows each)
    int warp_n = wid >> 2;         // 2 warps over N (64 cols each)
    int g = lane >> 2, tig = lane & 3;

    float acc[2][8][4];
#pragma unroll
    for (int i = 0; i < 2; i++)
#pragma unroll
        for (int j = 0; j < 8; j++)
#pragma unroll
            for (int c = 0; c < 4; c++) acc[i][j][c] = 0.f;

    for (int kc = 0; kc < 256; kc += BK) {
        // ---- stage A: 128 rows x 32 k (hi/lo split) ----
        const float* abase = (kc < 128) ? mean : hin;
        int koff = (kc < 128) ? kc : kc - 128;
#pragma unroll
        for (int r = 0; r < 4; r++) {
            int f = t + r * 256;            // 0..1023
            int m = f >> 3, kq = f & 7;     // m 0..127, float4 index along k
            int gi = row0 + m;
            int ic = gi < n ? gi : n - 1;
            float4 v = *(const float4*)(abase + (size_t)ic * HID + koff + kq * 4);
#pragma unroll
            for (int j = 0; j < 4; j++) {
                float val = (&v.x)[j];
                uint32_t h = f2tf(val);
                uint32_t l = f2tf(val - __uint_as_float(h));
                As_hi[(kq * 4 + j) * LDP + m] = h;
                As_lo[(kq * 4 + j) * LDP + m] = l;
            }
        }
        // ---- stage B: 32 k rows x 128 n (hi/lo split) ----
#pragma unroll
        for (int r = 0; r < 4; r++) {
            int f = t + r * 256;
            int kb = f >> 5, q = f & 31;    // kb 0..31, q*4 col
            int kg = kc + kb;
            const float* wsrc = (kg < 128) ? (wl + (size_t)kg * HID)
                                           : (wr + (size_t)(kg - 128) * HID);
            float4 v = *(const float4*)(wsrc + q * 4);
#pragma unroll
            for (int j = 0; j < 4; j++) {
                float val = (&v.x)[j];
                uint32_t h = f2tf(val);
                uint32_t l = f2tf(val - __uint_as_float(h));
                Bs_hi[kb * LDP + q * 4 + j] = h;
                Bs_lo[kb * LDP + q * 4 + j] = l;
            }
        }
        __syncthreads();

#pragma unroll
        for (int ks = 0; ks < BK / 8; ks++) {
            int k0 = ks * 8;
            uint32_t ah[2][4], al[2][4];
#pragma unroll
            for (int mi = 0; mi < 2; mi++) {
                int m0 = warp_m * 32 + mi * 16;
                ah[mi][0] = As_hi[(k0 + tig) * LDP + m0 + g];
                ah[mi][1] = As_hi[(k0 + tig) * LDP + m0 + g + 8];
                ah[mi][2] = As_hi[(k0 + tig + 4) * LDP + m0 + g];
                ah[mi][3] = As_hi[(k0 + tig + 4) * LDP + m0 + g + 8];
                al[mi][0] = As_lo[(k0 + tig) * LDP + m0 + g];
                al[mi][1] = As_lo[(k0 + tig) * LDP + m0 + g + 8];
                al[mi][2] = As_lo[(k0 + tig + 4) * LDP + m0 + g];
                al[mi][3] = As_lo[(k0 + tig + 4) * LDP + m0 + g + 8];
            }
#pragma unroll
            for (int nt = 0; nt < 8; nt++) {
                int n0 = warp_n * 64 + nt * 8;
                uint32_t bh0 = Bs_hi[(k0 + tig) * LDP + n0 + g];
                uint32_t bh1 = Bs_hi[(k0 + tig + 4) * LDP + n0 + g];
                uint32_t bl0 = Bs_lo[(k0 + tig) * LDP + n0 + g];
                uint32_t bl1 = Bs_lo[(k0 + tig + 4) * LDP + n0 + g];
#pragma unroll
                for (int mi = 0; mi < 2; mi++) {
                    mma_tf32(acc[mi][nt], ah[mi][0], ah[mi][1], ah[mi][2], ah[mi][3], bh0, bh1);
                    mma_tf32(acc[mi][nt], ah[mi][0], ah[mi][1], ah[mi][2], ah[mi][3], bl0, bl1);
                    mma_tf32(acc[mi][nt], al[mi][0], al[mi][1], al[mi][2], al[mi][3], bh0, bh1);
                }
            }
        }
        __syncthreads();
    }

    // ---- epilogue: +bias, row L2 norm across 128 cols, tanh ----
    float2 bv[8];
#pragma unroll
    for (int nt = 0; nt < 8; nt++)
        bv[nt] = *(const float2*)(bias + warp_n * 64 + nt * 8 + 2 * tig);

#pragma unroll
    for (int mi = 0; mi < 2; mi++) {
#pragma unroll
        for (int h = 0; h < 2; h++) {
            float ss = 0.f;
#pragma unroll
            for (int nt = 0; nt < 8; nt++) {
                acc[mi][nt][2 * h]     += bv[nt].x;
                acc[mi][nt][2 * h + 1] += bv[nt].y;
                ss += acc[mi][nt][2 * h] * acc[mi][nt][2 * h]
                    + acc[mi][nt][2 * h + 1] * acc[mi][nt][2 * h + 1];
            }
            ss += __shfl_xor_sync(0xffffffffu, ss, 1);
            ss += __shfl_xor_sync(0xffffffffu, ss, 2);
            if (tig == 0)
                ss_part[warp_n * BM + warp_m * 32 + mi * 16 + h * 8 + g] = ss;
        }
    }
    __syncthreads();

#pragma unroll
    for (int mi = 0; mi < 2; mi++) {
#pragma unroll
        for (int h = 0; h < 2; h++) {
            int rloc = warp_m * 32 + mi * 16 + h * 8 + g;
            int gi = row0 + rloc;
            if (gi >= n) continue;
            float tot = ss_part[rloc] + ss_part[BM + rloc];
            float invn = 1.f / fmaxf(sqrtf(tot), 1e-12f);
#pragma unroll
            for (int nt = 0; nt < 8; nt++) {
                float2 o;
                o.x = tanhf(acc[mi][nt][2 * h] * invn);
                o.y = tanhf(acc[mi][nt][2 * h + 1] * invn);
                *(float2*)(out + (size_t)gi * HID + warp_n * 64 + nt * 8 + 2 * tig) = o;
            }
        }
    }
}

// ---------------- launch ----------------
extern "C" void kernel_launch(void* const* d_in, const int* in_sizes, int n_in,
                              void* d_out, int out_size) {
    const float* x       = (const float*)d_in[0];
    const int*   ei_conn = (const int*)d_in[1];
    const int*   ei_dest = (const int*)d_in[2];
    const float* w_l1 = (const float*)d_in[3];
    const float* w_r1 = (const float*)d_in[4];
    const float* b1   = (const float*)d_in[5];
    const float* w_l2 = (const float*)d_in[6];
    const float* w_r2 = (const float*)d_in[7];
    const float* b2   = (const float*)d_in[8];
    const float* w_l3 = (const float*)d_in[9];
    const float* w_r3 = (const float*)d_in[10];
    const float* b3   = (const float*)d_in[11];
    float* out = (float*)d_out;

    const int n = N_NODES;
    const int E = in_sizes[1] / 2;

    float *p_h1, *p_h2, *p_agg, *p_agg8;
    int *p_cnt_c, *p_cnt_d, *p_rp_c, *p_rp_d, *p_cur_c, *p_cur_d, *p_src_c, *p_src_d;
    cudaGetSymbolAddress((void**)&p_h1, g_h1);
    cudaGetSymbolAddress((void**)&p_h2, g_h2);
    cudaGetSymbolAddress((void**)&p_agg, g_agg);
    cudaGetSymbolAddress((void**)&p_agg8, g_agg8);
    cudaGetSymbolAddress((void**)&p_cnt_c, g_cnt_c);
    cudaGetSymbolAddress((void**)&p_cnt_d, g_cnt_d);
    cudaGetSymbolAddress((void**)&p_rp_c, g_rp_c);
    cudaGetSymbolAddress((void**)&p_rp_d, g_rp_d);
    cudaGetSymbolAddress((void**)&p_cur_c, g_cur_c);
    cudaGetSymbolAddress((void**)&p_cur_d, g_cur_d);
    cudaGetSymbolAddress((void**)&p_src_c, g_src_c);
    cudaGetSymbolAddress((void**)&p_src_d, g_src_d);

    const int SMEM = (4 * BK * LDP) * 4 + 2 * BM * 4;  // 68608 bytes
    static bool attr_set = false;
    if (!attr_set) {
        cudaFuncSetAttribute(layer23_tc, cudaFuncAttributeMaxDynamicSharedMemorySize, SMEM);
        attr_set = true;
    }

    // ---- CSR build for both edge lists ----
    zero_u32_2<<<(n + 255) / 256, 256>>>(p_cnt_c, p_cnt_d, n);
    hist_kernel<<<2048, 256>>>(ei_conn, ei_dest, E, p_cnt_c, p_cnt_d);
    scan2_kernel<<<2, 1024>>>(p_cnt_c, p_rp_c, p_cur_c, p_cnt_d, p_rp_d, p_cur_d, n);
    fill_kernel<<<2048, 256>>>(ei_conn, ei_dest, E, p_cur_c, p_cur_d, p_src_c, p_src_d);

    // ---- layer 1 (conn, d=8) ----
    gather8<<<(n * 8 + 255) / 256, 256>>>(x, p_rp_c, p_src_c, p_agg8, n);
    layer1_kernel<<<(n + 7) / 8, 256>>>(x, p_agg8, w_l1, w_r1, b1, p_h1, n);

    // ---- layer 2 (dest, d=128) ----
    gather128<<<(n * 32 + 255) / 256, 256>>>(p_h1, p_rp_d, p_src_d, p_agg, n);
    layer23_tc<<<(n + BM - 1) / BM, 256, SMEM>>>(p_h1, p_agg, w_l2, w_r2, b2, p_h2, n);

    // ---- layer 3 (conn, d=128) ----
    gather128<<<(n * 32 + 255) / 256, 256>>>(p_h2, p_rp_c, p_src_c, p_agg, n);
    layer23_tc<<<(n + BM - 1) / BM, 256, SMEM>>>(p_h2, p_agg, w_l3, w_r3, b3, out, n);
}

// round 4
// speedup vs baseline: 1.4820x; 1.2320x over previous
#include <cuda_runtime.h>
#include <cuda_bf16.h>
#include <cstdint>

#define N_NODES 100000
#define N_EDGES 1600000
#define HID 128
#define IN_DIM 8

// ---------------- scratch (static __device__, no allocation) ----------------
__device__ float g_h1[(size_t)N_NODES * HID];
__device__ float g_h2[(size_t)N_NODES * HID];
__device__ float g_agg[(size_t)N_NODES * HID];
__device__ int g_cnt_c[N_NODES];
__device__ int g_cnt_d[N_NODES];
__device__ int g_rp_c[N_NODES + 1];
__device__ int g_rp_d[N_NODES + 1];
__device__ int g_cur_c[N_NODES];
__device__ int g_cur_d[N_NODES];
__device__ int g_src_c[N_EDGES];
__device__ int g_src_d[N_EDGES];

// ---------------- small utility kernels ----------------
__global__ void zero_u32_2(int* a, int* b, int n) {
    int i = blockIdx.x * blockDim.x + threadIdx.x;
    int st = gridDim.x * blockDim.x;
    for (; i < n; i += st) { a[i] = 0; b[i] = 0; }
}

__global__ void hist_kernel(const int* __restrict__ eic, const int* __restrict__ eid,
                            int E, int* cc, int* cd) {
    int i = blockIdx.x * blockDim.x + threadIdx.x;
    int st = gridDim.x * blockDim.x;
    for (; i < E; i += st) {
        atomicAdd(&cc[eic[E + i]], 1);
        atomicAdd(&cd[eid[E + i]], 1);
    }
}

__global__ __launch_bounds__(1024) void scan2_kernel(
    const int* c0, int* rp0, int* cur0,
    const int* c1, int* rp1, int* cur1, int n) {
    const int* cnt = blockIdx.x ? c1 : c0;
    int* rp  = blockIdx.x ? rp1 : rp0;
    int* cur = blockIdx.x ? cur1 : cur0;
    __shared__ int s[1024];
    int t = threadIdx.x;
    int per = (n + 1023) / 1024;
    int beg = t * per;
    int end = min(beg + per, n);
    int sum = 0;
    for (int i = beg; i < end; i++) sum += cnt[i];
    s[t] = sum;
    __syncthreads();
    for (int off = 1; off < 1024; off <<= 1) {
        int v = (t >= off) ? s[t - off] : 0;
        __syncthreads();
        s[t] += v;
        __syncthreads();
    }
    int run = s[t] - sum;
    for (int i = beg; i < end; i++) {
        rp[i] = run;
        cur[i] = run;
        run += cnt[i];
    }
    if (t == 1023) rp[n] = s[1023];
}

__global__ void fill_kernel(const int* __restrict__ eic, const int* __restrict__ eid,
                            int E, int* curc, int* curd,
                            int* __restrict__ srcc, int* __restrict__ srcd) {
    int i = blockIdx.x * blockDim.x + threadIdx.x;
    int st = gridDim.x * blockDim.x;
    for (; i < E; i += st) {
        int s = eic[i], d = eic[E + i];
        int p = atomicAdd(&curc[d], 1);
        srcc[p] = s;
        s = eid[i]; d = eid[E + i];
        p = atomicAdd(&curd[d], 1);
        srcd[p] = s;
    }
}

// ---------------- pull-style gather-mean, d=128: one warp per node ----------------
__global__ void gather128(const float* __restrict__ h, const int* __restrict__ rp,
                          const int* __restrict__ src, float* __restrict__ out, int n) {
    int node = (blockIdx.x * blockDim.x + threadIdx.x) >> 5;
    int lane = threadIdx.x & 31;
    if (node >= n) return;
    int b = __ldg(rp + node), e = __ldg(rp + node + 1);
    float4 acc = make_float4(0.f, 0.f, 0.f, 0.f);
    int j = b;
    for (; j + 4 <= e; j += 4) {
        int s0 = __ldg(src + j), s1 = __ldg(src + j + 1);
        int s2 = __ldg(src + j + 2), s3 = __ldg(src + j + 3);
        float4 v0 = *(const float4*)(h + (size_t)s0 * HID + lane * 4);
        float4 v1 = *(const float4*)(h + (size_t)s1 * HID + lane * 4);
        float4 v2 = *(const float4*)(h + (size_t)s2 * HID + lane * 4);
        float4 v3 = *(const float4*)(h + (size_t)s3 * HID + lane * 4);
        acc.x += (v0.x + v1.x) + (v2.x + v3.x);
        acc.y += (v0.y + v1.y) + (v2.y + v3.y);
        acc.z += (v0.z + v1.z) + (v2.z + v3.z);
        acc.w += (v0.w + v1.w) + (v2.w + v3.w);
    }
    for (; j < e; j++) {
        int s0 = __ldg(src + j);
        float4 v0 = *(const float4*)(h + (size_t)s0 * HID + lane * 4);
        acc.x += v0.x; acc.y += v0.y; acc.z += v0.z; acc.w += v0.w;
    }
    float inv = 1.f / fmaxf((float)(e - b), 1.f);
    acc.x *= inv; acc.y *= inv; acc.z *= inv; acc.w *= inv;
    *(float4*)(out + (size_t)node * HID + lane * 4) = acc;
}

// ---------------- layer 1 fused: gather-mean(d=8) + GEMM + norm + tanh ----------------
__global__ void layer1_fused(const float* __restrict__ x,
                             const int* __restrict__ rp, const int* __restrict__ src,
                             const float* __restrict__ wl, const float* __restrict__ wr,
                             const float* __restrict__ bias,
                             float* __restrict__ out, int n) {
    __shared__ float s_wl[IN_DIM * HID];
    __shared__ float s_wr[IN_DIM * HID];
    __shared__ float s_b[HID];
    for (int i = threadIdx.x; i < IN_DIM * HID; i += blockDim.x) {
        s_wl[i] = wl[i];
        s_wr[i] = wr[i];
    }
    if (threadIdx.x < HID) s_b[threadIdx.x] = bias[threadIdx.x];
    __syncthreads();

    int warp = threadIdx.x >> 5, lane = threadIdx.x & 31;
    int node = blockIdx.x * (blockDim.x >> 5) + warp;
    if (node >= n) return;
    int grp = lane >> 3, dim = lane & 7;

    // each of 4 groups (8 lanes) accumulates over strided neighbors
    int b = __ldg(rp + node), e = __ldg(rp + node + 1);
    float acc8 = 0.f;
    for (int j = b + grp; j < e; j += 4) {
        int s0 = __ldg(src + j);
        acc8 += __ldg(x + (size_t)s0 * IN_DIM + dim);
    }
    acc8 += __shfl_xor_sync(0xffffffffu, acc8, 8);
    acc8 += __shfl_xor_sync(0xffffffffu, acc8, 16);
    acc8 *= 1.f / fmaxf((float)(e - b), 1.f);  // mean, valid on all lanes (per dim)

    float my_x = __ldg(x + (size_t)node * IN_DIM + dim);

    float xs[8], as[8];
#pragma unroll
    for (int k = 0; k < 8; k++) {
        xs[k] = __shfl_sync(0xffffffffu, my_x, k);
        as[k] = __shfl_sync(0xffffffffu, acc8, k);
    }
    float acc[4];
#pragma unroll
    for (int c = 0; c < 4; c++) {
        int j = lane + 32 * c;
        float a = s_b[j];
#pragma unroll
        for (int k = 0; k < 8; k++)
            a += as[k] * s_wl[k * HID + j] + xs[k] * s_wr[k * HID + j];
        acc[c] = a;
    }
    float ss = acc[0] * acc[0] + acc[1] * acc[1] + acc[2] * acc[2] + acc[3] * acc[3];
#pragma unroll
    for (int o = 16; o >= 1; o >>= 1) ss += __shfl_xor_sync(0xffffffffu, ss, o);
    float invn = 1.f / fmaxf(sqrtf(ss), 1e-12f);
#pragma unroll
    for (int c = 0; c < 4; c++)
        out[(size_t)node * HID + lane + 32 * c] = tanhf(acc[c] * invn);
}

// ---------------- bf16-split tensor-core GEMM, layers 2/3 ----------------
// out[M,128] = tanh(l2norm([mean|hin] @ [wl;wr] + b)); 3-term bf16 split (hh+hl+lh).
#define BM 128
#define BN 128
#define BK 32          // fp32 k per tile
#define KW 16          // packed bf16-pair words per tile (BK/2)
#define LDP 137        // padded minor stride (words)

__device__ __forceinline__ uint32_t pack_hi(float x0, float x1, float& r0, float& r1) {
    __nv_bfloat162 h = __floats2bfloat162_rn(x0, x1);
    r0 = x0 - __bfloat162float(h.x);
    r1 = x1 - __bfloat162float(h.y);
    return *(uint32_t*)&h;
}
__device__ __forceinline__ uint32_t pack_lo(float r0, float r1) {
    __nv_bfloat162 l = __floats2bfloat162_rn(r0, r1);
    return *(uint32_t*)&l;
}

__device__ __forceinline__ void mma_bf16(float* c, uint32_t a0, uint32_t a1,
                                         uint32_t a2, uint32_t a3,
                                         uint32_t b0, uint32_t b1) {
    asm volatile(
        "mma.sync.aligned.m16n8k16.row.col.f32.bf16.bf16.f32 "
        "{%0,%1,%2,%3}, {%4,%5,%6,%7}, {%8,%9}, {%0,%1,%2,%3};"
        : "+f"(c[0]), "+f"(c[1]), "+f"(c[2]), "+f"(c[3])
        : "r"(a0), "r"(a1), "r"(a2), "r"(a3), "r"(b0), "r"(b1));
}

__global__ __launch_bounds__(256, 2) void layer23_tc(
    const float* __restrict__ hin, const float* __restrict__ mean,
    const float* __restrict__ wl, const float* __restrict__ wr,
    const float* __restrict__ bias, float* __restrict__ out, int n) {
    __shared__ uint32_t Ah[KW * LDP];
    __shared__ uint32_t Al[KW * LDP];
    __shared__ uint32_t Bh[KW * LDP];
    __shared__ uint32_t Bl[KW * LDP];
    __shared__ float ss_part[2 * BM];

    int t = threadIdx.x;
    int row0 = blockIdx.x * BM;
    int wid = t >> 5, lane = t & 31;
    int warp_m = wid & 3;          // 4 warps over M (32 rows each)
    int warp_n = wid >> 2;         // 2 warps over N (64 cols each)
    int g = lane >> 2, tig = lane & 3;

    float acc[2][8][4];
#pragma unroll
    for (int i = 0; i < 2; i++)
#pragma unroll
        for (int j = 0; j < 8; j++)
#pragma unroll
            for (int c = 0; c < 4; c++) acc[i][j][c] = 0.f;

    for (int kc = 0; kc < 256; kc += BK) {
        const float* abase = (kc < 128) ? mean : hin;
        int koff = (kc < 128) ? kc : kc - 128;
        // ---- stage A: 128 rows x 32 k, packed bf16 pairs hi/lo ----
#pragma unroll
        for (int r = 0; r < 4; r++) {
            int f = t + r * 256;            // 0..1023
            int m = f >> 3, kq = f & 7;     // row, float4 index
            int gi = row0 + m;
            int ic = gi < n ? gi : n - 1;
            float4 v = *(const float4*)(abase + (size_t)ic * HID + koff + kq * 4);
            float r0, r1, r2, r3;
            uint32_t h0 = pack_hi(v.x, v.y, r0, r1);
            uint32_t h1 = pack_hi(v.z, v.w, r2, r3);
            Ah[(2 * kq) * LDP + m] = h0;
            Ah[(2 * kq + 1) * LDP + m] = h1;
            Al[(2 * kq) * LDP + m] = pack_lo(r0, r1);
            Al[(2 * kq + 1) * LDP + m] = pack_lo(r2, r3);
        }
        // ---- stage B: 32 k rows x 128 n -> words (n-major within row kk) ----
        const float* wbase = (kc < 128) ? wl : wr;
        int wkoff = (kc < 128) ? kc : kc - 128;
#pragma unroll
        for (int r = 0; r < 2; r++) {
            int f = t + r * 256;            // 0..511
            int kk = f >> 5, q = f & 31;    // word row 0..15, n-quad 0..31
            const float* w0 = wbase + (size_t)(wkoff + 2 * kk) * HID + q * 4;
            const float* w1 = w0 + HID;
            float4 va = *(const float4*)w0;  // k even row
            float4 vb = *(const float4*)w1;  // k odd row
            float r0, r1;
#pragma unroll
            for (int j = 0; j < 4; j++) {
                uint32_t h = pack_hi((&va.x)[j], (&vb.x)[j], r0, r1);
                Bh[kk * LDP + q * 4 + j] = h;
                Bl[kk * LDP + q * 4 + j] = pack_lo(r0, r1);
            }
        }
        __syncthreads();

#pragma unroll
        for (int s = 0; s < 2; s++) {       // two k16 steps per tile
            int k0 = s * 8;
            uint32_t ah[2][4], al[2][4];
#pragma unroll
            for (int mi = 0; mi < 2; mi++) {
                int m0 = warp_m * 32 + mi * 16;
                ah[mi][0] = Ah[(k0 + tig) * LDP + m0 + g];
                ah[mi][1] = Ah[(k0 + tig) * LDP + m0 + g + 8];
                ah[mi][2] = Ah[(k0 + tig + 4) * LDP + m0 + g];
                ah[mi][3] = Ah[(k0 + tig + 4) * LDP + m0 + g + 8];
                al[mi][0] = Al[(k0 + tig) * LDP + m0 + g];
                al[mi][1] = Al[(k0 + tig) * LDP + m0 + g + 8];
                al[mi][2] = Al[(k0 + tig + 4) * LDP + m0 + g];
                al[mi][3] = Al[(k0 + tig + 4) * LDP + m0 + g + 8];
            }
#pragma unroll
            for (int nt = 0; nt < 8; nt++) {
                int n0 = warp_n * 64 + nt * 8;
                uint32_t bh0 = Bh[(k0 + tig) * LDP + n0 + g];
                uint32_t bh1 = Bh[(k0 + tig + 4) * LDP + n0 + g];
                uint32_t bl0 = Bl[(k0 + tig) * LDP + n0 + g];
                uint32_t bl1 = Bl[(k0 + tig + 4) * LDP + n0 + g];
#pragma unroll
                for (int mi = 0; mi < 2; mi++) {
                    mma_bf16(acc[mi][nt], ah[mi][0], ah[mi][1], ah[mi][2], ah[mi][3], bh0, bh1);
                    mma_bf16(acc[mi][nt], ah[mi][0], ah[mi][1], ah[mi][2], ah[mi][3], bl0, bl1);
                    mma_bf16(acc[mi][nt], al[mi][0], al[mi][1], al[mi][2], al[mi][3], bh0, bh1);
                }
            }
        }
        __syncthreads();
    }

    // ---- epilogue: +bias, row L2 norm across 128 cols, tanh ----
    float2 bv[8];
#pragma unroll
    for (int nt = 0; nt < 8; nt++)
        bv[nt] = *(const float2*)(bias + warp_n * 64 + nt * 8 + 2 * tig);

#pragma unroll
    for (int mi = 0; mi < 2; mi++) {
#pragma unroll
        for (int h = 0; h < 2; h++) {
            float ss = 0.f;
#pragma unroll
            for (int nt = 0; nt < 8; nt++) {
                acc[mi][nt][2 * h]     += bv[nt].x;
                acc[mi][nt][2 * h + 1] += bv[nt].y;
                ss += acc[mi][nt][2 * h] * acc[mi][nt][2 * h]
                    + acc[mi][nt][2 * h + 1] * acc[mi][nt][2 * h + 1];
            }
            ss += __shfl_xor_sync(0xffffffffu, ss, 1);
            ss += __shfl_xor_sync(0xffffffffu, ss, 2);
            if (tig == 0)
                ss_part[warp_n * BM + warp_m * 32 + mi * 16 + h * 8 + g] = ss;
        }
    }
    __syncthreads();

#pragma unroll
    for (int mi = 0; mi < 2; mi++) {
#pragma unroll
        for (int h = 0; h < 2; h++) {
            int rloc = warp_m * 32 + mi * 16 + h * 8 + g;
            int gi = row0 + rloc;
            if (gi >= n) continue;
            float tot = ss_part[rloc] + ss_part[BM + rloc];
            float invn = 1.f / fmaxf(sqrtf(tot), 1e-12f);
#pragma unroll
            for (int nt = 0; nt < 8; nt++) {
                float2 o;
                o.x = tanhf(acc[mi][nt][2 * h] * invn);
                o.y = tanhf(acc[mi][nt][2 * h + 1] * invn);
                *(float2*)(out + (size_t)gi * HID + warp_n * 64 + nt * 8 + 2 * tig) = o;
            }
        }
    }
}

// ---------------- launch ----------------
extern "C" void kernel_launch(void* const* d_in, const int* in_sizes, int n_in,
                              void* d_out, int out_size) {
    const float* x       = (const float*)d_in[0];
    const int*   ei_conn = (const int*)d_in[1];
    const int*   ei_dest = (const int*)d_in[2];
    const float* w_l1 = (const float*)d_in[3];
    const float* w_r1 = (const float*)d_in[4];
    const float* b1   = (const float*)d_in[5];
    const float* w_l2 = (const float*)d_in[6];
    const float* w_r2 = (const float*)d_in[7];
    const float* b2   = (const float*)d_in[8];
    const float* w_l3 = (const float*)d_in[9];
    const float* w_r3 = (const float*)d_in[10];
    const float* b3   = (const float*)d_in[11];
    float* out = (float*)d_out;

    const int n = N_NODES;
    const int E = in_sizes[1] / 2;

    float *p_h1, *p_h2, *p_agg;
    int *p_cnt_c, *p_cnt_d, *p_rp_c, *p_rp_d, *p_cur_c, *p_cur_d, *p_src_c, *p_src_d;
    cudaGetSymbolAddress((void**)&p_h1, g_h1);
    cudaGetSymbolAddress((void**)&p_h2, g_h2);
    cudaGetSymbolAddress((void**)&p_agg, g_agg);
    cudaGetSymbolAddress((void**)&p_cnt_c, g_cnt_c);
    cudaGetSymbolAddress((void**)&p_cnt_d, g_cnt_d);
    cudaGetSymbolAddress((void**)&p_rp_c, g_rp_c);
    cudaGetSymbolAddress((void**)&p_rp_d, g_rp_d);
    cudaGetSymbolAddress((void**)&p_cur_c, g_cur_c);
    cudaGetSymbolAddress((void**)&p_cur_d, g_cur_d);
    cudaGetSymbolAddress((void**)&p_src_c, g_src_c);
    cudaGetSymbolAddress((void**)&p_src_d, g_src_d);

    // ---- CSR build for both edge lists ----
    zero_u32_2<<<(n + 255) / 256, 256>>>(p_cnt_c, p_cnt_d, n);
    hist_kernel<<<2048, 256>>>(ei_conn, ei_dest, E, p_cnt_c, p_cnt_d);
    scan2_kernel<<<2, 1024>>>(p_cnt_c, p_rp_c, p_cur_c, p_cnt_d, p_rp_d, p_cur_d, n);
    fill_kernel<<<2048, 256>>>(ei_conn, ei_dest, E, p_cur_c, p_cur_d, p_src_c, p_src_d);

    // ---- layer 1 (conn, d=8), gather fused ----
    layer1_fused<<<(n + 7) / 8, 256>>>(x, p_rp_c, p_src_c, w_l1, w_r1, b1, p_h1, n);

    // ---- layer 2 (dest, d=128) ----
    gather128<<<(n * 32 + 255) / 256, 256>>>(p_h1, p_rp_d, p_src_d, p_agg, n);
    layer23_tc<<<(n + BM - 1) / BM, 256>>>(p_h1, p_agg, w_l2, w_r2, b2, p_h2, n);

    // ---- layer 3 (conn, d=128) ----
    gather128<<<(n * 32 + 255) / 256, 256>>>(p_h2, p_rp_c, p_src_c, p_agg, n);
    layer23_tc<<<(n + BM - 1) / BM, 256>>>(p_h2, p_agg, w_l3, w_r3, b3, out, n);
}

// round 5
// speedup vs baseline: 1.5350x; 1.0358x over previous
#include <cuda_runtime.h>
#include <cuda_bf16.h>
#include <cuda_fp16.h>
#include <cstdint>

#define N_NODES 100000
#define N_EDGES 1600000
#define HID 128
#define IN_DIM 8

// ---------------- scratch (static __device__, no allocation) ----------------
__device__ float g_h1[(size_t)N_NODES * HID];
__device__ float g_h2[(size_t)N_NODES * HID];
__device__ __half g_h1h[(size_t)N_NODES * HID];
__device__ __half g_h2h[(size_t)N_NODES * HID];
__device__ float g_agg[(size_t)N_NODES * HID];
__device__ int g_cnt_c[N_NODES];
__device__ int g_cnt_d[N_NODES];
__device__ int g_rp_c[N_NODES + 1];
__device__ int g_rp_d[N_NODES + 1];
__device__ int g_cur_c[N_NODES];
__device__ int g_cur_d[N_NODES];
__device__ int g_src_c[N_EDGES];
__device__ int g_src_d[N_EDGES];

// ---------------- small utility kernels ----------------
__global__ void zero_u32_2(int* a, int* b, int n) {
    int i = blockIdx.x * blockDim.x + threadIdx.x;
    int st = gridDim.x * blockDim.x;
    for (; i < n; i += st) { a[i] = 0; b[i] = 0; }
}

__global__ void hist_kernel(const int* __restrict__ eic, const int* __restrict__ eid,
                            int E, int* cc, int* cd) {
    int i = blockIdx.x * blockDim.x + threadIdx.x;
    int st = gridDim.x * blockDim.x;
    for (; i < E; i += st) {
        atomicAdd(&cc[eic[E + i]], 1);
        atomicAdd(&cd[eid[E + i]], 1);
    }
}

__global__ __launch_bounds__(1024) void scan2_kernel(
    const int* c0, int* rp0, int* cur0,
    const int* c1, int* rp1, int* cur1, int n) {
    const int* cnt = blockIdx.x ? c1 : c0;
    int* rp  = blockIdx.x ? rp1 : rp0;
    int* cur = blockIdx.x ? cur1 : cur0;
    __shared__ int s[1024];
    int t = threadIdx.x;
    int per = (n + 1023) / 1024;
    int beg = t * per;
    int end = min(beg + per, n);
    int sum = 0;
    for (int i = beg; i < end; i++) sum += cnt[i];
    s[t] = sum;
    __syncthreads();
    for (int off = 1; off < 1024; off <<= 1) {
        int v = (t >= off) ? s[t - off] : 0;
        __syncthreads();
        s[t] += v;
        __syncthreads();
    }
    int run = s[t] - sum;
    for (int i = beg; i < end; i++) {
        rp[i] = run;
        cur[i] = run;
        run += cnt[i];
    }
    if (t == 1023) rp[n] = s[1023];
}

__global__ void fill_kernel(const int* __restrict__ eic, const int* __restrict__ eid,
                            int E, int* curc, int* curd,
                            int* __restrict__ srcc, int* __restrict__ srcd) {
    int i = blockIdx.x * blockDim.x + threadIdx.x;
    int st = gridDim.x * blockDim.x;
    for (; i < E; i += st) {
        int s = eic[i], d = eic[E + i];
        int p = atomicAdd(&curc[d], 1);
        srcc[p] = s;
        s = eid[i]; d = eid[E + i];
        p = atomicAdd(&curd[d], 1);
        srcd[p] = s;
    }
}

// ---------------- gather-mean over fp16 rows, d=128: one warp per node ----------------
__global__ void gather128h(const __half* __restrict__ h, const int* __restrict__ rp,
                           const int* __restrict__ src, float* __restrict__ out, int n) {
    int node = (blockIdx.x * blockDim.x + threadIdx.x) >> 5;
    int lane = threadIdx.x & 31;
    if (node >= n) return;
    int b = __ldg(rp + node), e = __ldg(rp + node + 1);
    float4 acc = make_float4(0.f, 0.f, 0.f, 0.f);
    int j = b;
    for (; j + 4 <= e; j += 4) {
        int s0 = __ldg(src + j), s1 = __ldg(src + j + 1);
        int s2 = __ldg(src + j + 2), s3 = __ldg(src + j + 3);
        uint2 r0 = *(const uint2*)(h + (size_t)s0 * HID + lane * 4);
        uint2 r1 = *(const uint2*)(h + (size_t)s1 * HID + lane * 4);
        uint2 r2 = *(const uint2*)(h + (size_t)s2 * HID + lane * 4);
        uint2 r3 = *(const uint2*)(h + (size_t)s3 * HID + lane * 4);
#pragma unroll
        for (int q = 0; q < 4; q++) {
            uint2 r = q == 0 ? r0 : (q == 1 ? r1 : (q == 2 ? r2 : r3));
            float2 f0 = __half22float2(*(const __half2*)&r.x);
            float2 f1 = __half22float2(*(const __half2*)&r.y);
            acc.x += f0.x; acc.y += f0.y; acc.z += f1.x; acc.w += f1.y;
        }
    }
    for (; j < e; j++) {
        int s0 = __ldg(src + j);
        uint2 r = *(const uint2*)(h + (size_t)s0 * HID + lane * 4);
        float2 f0 = __half22float2(*(const __half2*)&r.x);
        float2 f1 = __half22float2(*(const __half2*)&r.y);
        acc.x += f0.x; acc.y += f0.y; acc.z += f1.x; acc.w += f1.y;
    }
    float inv = 1.f / fmaxf((float)(e - b), 1.f);
    acc.x *= inv; acc.y *= inv; acc.z *= inv; acc.w *= inv;
    *(float4*)(out + (size_t)node * HID + lane * 4) = acc;
}

// ---------------- layer 1 fused: gather-mean(d=8) + GEMM + norm + tanh ----------------
__global__ void layer1_fused(const float* __restrict__ x,
                             const int* __restrict__ rp, const int* __restrict__ src,
                             const float* __restrict__ wl, const float* __restrict__ wr,
                             const float* __restrict__ bias,
                             float* __restrict__ out, __half* __restrict__ outh, int n) {
    __shared__ float s_wl[IN_DIM * HID];
    __shared__ float s_wr[IN_DIM * HID];
    __shared__ float s_b[HID];
    for (int i = threadIdx.x; i < IN_DIM * HID; i += blockDim.x) {
        s_wl[i] = wl[i];
        s_wr[i] = wr[i];
    }
    if (threadIdx.x < HID) s_b[threadIdx.x] = bias[threadIdx.x];
    __syncthreads();

    int warp = threadIdx.x >> 5, lane = threadIdx.x & 31;
    int node = blockIdx.x * (blockDim.x >> 5) + warp;
    if (node >= n) return;
    int grp = lane >> 3, dim = lane & 7;

    int b = __ldg(rp + node), e = __ldg(rp + node + 1);
    float acc8 = 0.f;
    for (int j = b + grp; j < e; j += 4) {
        int s0 = __ldg(src + j);
        acc8 += __ldg(x + (size_t)s0 * IN_DIM + dim);
    }
    acc8 += __shfl_xor_sync(0xffffffffu, acc8, 8);
    acc8 += __shfl_xor_sync(0xffffffffu, acc8, 16);
    acc8 *= 1.f / fmaxf((float)(e - b), 1.f);

    float my_x = __ldg(x + (size_t)node * IN_DIM + dim);

    float xs[8], as[8];
#pragma unroll
    for (int k = 0; k < 8; k++) {
        xs[k] = __shfl_sync(0xffffffffu, my_x, k);
        as[k] = __shfl_sync(0xffffffffu, acc8, k);
    }
    float acc[4];
#pragma unroll
    for (int c = 0; c < 4; c++) {
        int j = lane + 32 * c;
        float a = s_b[j];
#pragma unroll
        for (int k = 0; k < 8; k++)
            a += as[k] * s_wl[k * HID + j] + xs[k] * s_wr[k * HID + j];
        acc[c] = a;
    }
    float ss = acc[0] * acc[0] + acc[1] * acc[1] + acc[2] * acc[2] + acc[3] * acc[3];
#pragma unroll
    for (int o = 16; o >= 1; o >>= 1) ss += __shfl_xor_sync(0xffffffffu, ss, o);
    float invn = 1.f / fmaxf(sqrtf(ss), 1e-12f);
#pragma unroll
    for (int c = 0; c < 4; c++) {
        float v = tanhf(acc[c] * invn);
        out[(size_t)node * HID + lane + 32 * c] = v;
        outh[(size_t)node * HID + lane + 32 * c] = __float2half(v);
    }
}

// ---------------- bf16-split tensor-core GEMM, layers 2/3 ----------------
#define BM 128
#define BN 128
#define BK 32
#define KW 16
#define LDP 137

__device__ __forceinline__ uint32_t pack_hi(float x0, float x1, float& r0, float& r1) {
    __nv_bfloat162 h = __floats2bfloat162_rn(x0, x1);
    r0 = x0 - __bfloat162float(h.x);
    r1 = x1 - __bfloat162float(h.y);
    return *(uint32_t*)&h;
}
__device__ __forceinline__ uint32_t pack_lo(float r0, float r1) {
    __nv_bfloat162 l = __floats2bfloat162_rn(r0, r1);
    return *(uint32_t*)&l;
}

__device__ __forceinline__ void mma_bf16(float* c, uint32_t a0, uint32_t a1,
                                         uint32_t a2, uint32_t a3,
                                         uint32_t b0, uint32_t b1) {
    asm volatile(
        "mma.sync.aligned.m16n8k16.row.col.f32.bf16.bf16.f32 "
        "{%0,%1,%2,%3}, {%4,%5,%6,%7}, {%8,%9}, {%0,%1,%2,%3};"
        : "+f"(c[0]), "+f"(c[1]), "+f"(c[2]), "+f"(c[3])
        : "r"(a0), "r"(a1), "r"(a2), "r"(a3), "r"(b0), "r"(b1));
}

__global__ __launch_bounds__(256, 2) void layer23_tc(
    const float* __restrict__ hin, const float* __restrict__ mean,
    const float* __restrict__ wl, const float* __restrict__ wr,
    const float* __restrict__ bias, float* __restrict__ out,
    __half* __restrict__ outh, int n) {
    __shared__ uint32_t Ah[KW * LDP];
    __shared__ uint32_t Al[KW * LDP];
    __shared__ uint32_t Bh[KW * LDP];
    __shared__ uint32_t Bl[KW * LDP];
    __shared__ float ss_part[2 * BM];

    int t = threadIdx.x;
    int row0 = blockIdx.x * BM;
    int wid = t >> 5, lane = t & 31;
    int warp_m = wid & 3;
    int warp_n = wid >> 2;
    int g = lane >> 2, tig = lane & 3;

    float acc[2][8][4];
#pragma unroll
    for (int i = 0; i < 2; i++)
#pragma unroll
        for (int j = 0; j < 8; j++)
#pragma unroll
            for (int c = 0; c < 4; c++) acc[i][j][c] = 0.f;

    for (int kc = 0; kc < 256; kc += BK) {
        const float* abase = (kc < 128) ? mean : hin;
        int koff = (kc < 128) ? kc : kc - 128;
#pragma unroll
        for (int r = 0; r < 4; r++) {
            int f = t + r * 256;
            int m = f >> 3, kq = f & 7;
            int gi = row0 + m;
            int ic = gi < n ? gi : n - 1;
            float4 v = *(const float4*)(abase + (size_t)ic * HID + koff + kq * 4);
            float r0, r1, r2, r3;
            uint32_t h0 = pack_hi(v.x, v.y, r0, r1);
            uint32_t h1 = pack_hi(v.z, v.w, r2, r3);
            Ah[(2 * kq) * LDP + m] = h0;
            Ah[(2 * kq + 1) * LDP + m] = h1;
            Al[(2 * kq) * LDP + m] = pack_lo(r0, r1);
            Al[(2 * kq + 1) * LDP + m] = pack_lo(r2, r3);
        }
        const float* wbase = (kc < 128) ? wl : wr;
        int wkoff = (kc < 128) ? kc : kc - 128;
#pragma unroll
        for (int r = 0; r < 2; r++) {
            int f = t + r * 256;
            int kk = f >> 5, q = f & 31;
            const float* w0 = wbase + (size_t)(wkoff + 2 * kk) * HID + q * 4;
            const float* w1 = w0 + HID;
            float4 va = *(const float4*)w0;
            float4 vb = *(const float4*)w1;
            float r0, r1;
#pragma unroll
            for (int j = 0; j < 4; j++) {
                uint32_t h = pack_hi((&va.x)[j], (&vb.x)[j], r0, r1);
                Bh[kk * LDP + q * 4 + j] = h;
                Bl[kk * LDP + q * 4 + j] = pack_lo(r0, r1);
            }
        }
        __syncthreads();

#pragma unroll
        for (int s = 0; s < 2; s++) {
            int k0 = s * 8;
            uint32_t ah[2][4], al[2][4];
#pragma unroll
            for (int mi = 0; mi < 2; mi++) {
                int m0 = warp_m * 32 + mi * 16;
                ah[mi][0] = Ah[(k0 + tig) * LDP + m0 + g];
                ah[mi][1] = Ah[(k0 + tig) * LDP + m0 + g + 8];
                ah[mi][2] = Ah[(k0 + tig + 4) * LDP + m0 + g];
                ah[mi][3] = Ah[(k0 + tig + 4) * LDP + m0 + g + 8];
                al[mi][0] = Al[(k0 + tig) * LDP + m0 + g];
                al[mi][1] = Al[(k0 + tig) * LDP + m0 + g + 8];
                al[mi][2] = Al[(k0 + tig + 4) * LDP + m0 + g];
                al[mi][3] = Al[(k0 + tig + 4) * LDP + m0 + g + 8];
            }
#pragma unroll
            for (int nt = 0; nt < 8; nt++) {
                int n0 = warp_n * 64 + nt * 8;
                uint32_t bh0 = Bh[(k0 + tig) * LDP + n0 + g];
                uint32_t bh1 = Bh[(k0 + tig + 4) * LDP + n0 + g];
                uint32_t bl0 = Bl[(k0 + tig) * LDP + n0 + g];
                uint32_t bl1 = Bl[(k0 + tig + 4) * LDP + n0 + g];
#pragma unroll
                for (int mi = 0; mi < 2; mi++) {
                    mma_bf16(acc[mi][nt], ah[mi][0], ah[mi][1], ah[mi][2], ah[mi][3], bh0, bh1);
                    mma_bf16(acc[mi][nt], ah[mi][0], ah[mi][1], ah[mi][2], ah[mi][3], bl0, bl1);
                    mma_bf16(acc[mi][nt], al[mi][0], al[mi][1], al[mi][2], al[mi][3], bh0, bh1);
                }
            }
        }
        __syncthreads();
    }

    float2 bv[8];
#pragma unroll
    for (int nt = 0; nt < 8; nt++)
        bv[nt] = *(const float2*)(bias + warp_n * 64 + nt * 8 + 2 * tig);

#pragma unroll
    for (int mi = 0; mi < 2; mi++) {
#pragma unroll
        for (int h = 0; h < 2; h++) {
            float ss = 0.f;
#pragma unroll
            for (int nt = 0; nt < 8; nt++) {
                acc[mi][nt][2 * h]     += bv[nt].x;
                acc[mi][nt][2 * h + 1] += bv[nt].y;
                ss += acc[mi][nt][2 * h] * acc[mi][nt][2 * h]
                    + acc[mi][nt][2 * h + 1] * acc[mi][nt][2 * h + 1];
            }
            ss += __shfl_xor_sync(0xffffffffu, ss, 1);
            ss += __shfl_xor_sync(0xffffffffu, ss, 2);
            if (tig == 0)
                ss_part[warp_n * BM + warp_m * 32 + mi * 16 + h * 8 + g] = ss;
        }
    }
    __syncthreads();

#pragma unroll
    for (int mi = 0; mi < 2; mi++) {
#pragma unroll
        for (int h = 0; h < 2; h++) {
            int rloc = warp_m * 32 + mi * 16 + h * 8 + g;
            int gi = row0 + rloc;
            if (gi >= n) continue;
            float tot = ss_part[rloc] + ss_part[BM + rloc];
            float invn = 1.f / fmaxf(sqrtf(tot), 1e-12f);
#pragma unroll
            for (int nt = 0; nt < 8; nt++) {
                float2 o;
                o.x = tanhf(acc[mi][nt][2 * h] * invn);
                o.y = tanhf(acc[mi][nt][2 * h + 1] * invn);
                size_t off = (size_t)gi * HID + warp_n * 64 + nt * 8 + 2 * tig;
                *(float2*)(out + off) = o;
                if (outh) *(__half2*)(outh + off) = __floats2half2_rn(o.x, o.y);
            }
        }
    }
}

// ---------------- launch ----------------
extern "C" void kernel_launch(void* const* d_in, const int* in_sizes, int n_in,
                              void* d_out, int out_size) {
    const float* x       = (const float*)d_in[0];
    const int*   ei_conn = (const int*)d_in[1];
    const int*   ei_dest = (const int*)d_in[2];
    const float* w_l1 = (const float*)d_in[3];
    const float* w_r1 = (const float*)d_in[4];
    const float* b1   = (const float*)d_in[5];
    const float* w_l2 = (const float*)d_in[6];
    const float* w_r2 = (const float*)d_in[7];
    const float* b2   = (const float*)d_in[8];
    const float* w_l3 = (const float*)d_in[9];
    const float* w_r3 = (const float*)d_in[10];
    const float* b3   = (const float*)d_in[11];
    float* out = (float*)d_out;

    const int n = N_NODES;
    const int E = in_sizes[1] / 2;

    float *p_h1, *p_h2, *p_agg;
    __half *p_h1h, *p_h2h;
    int *p_cnt_c, *p_cnt_d, *p_rp_c, *p_rp_d, *p_cur_c, *p_cur_d, *p_src_c, *p_src_d;
    cudaGetSymbolAddress((void**)&p_h1, g_h1);
    cudaGetSymbolAddress((void**)&p_h2, g_h2);
    cudaGetSymbolAddress((void**)&p_h1h, g_h1h);
    cudaGetSymbolAddress((void**)&p_h2h, g_h2h);
    cudaGetSymbolAddress((void**)&p_agg, g_agg);
    cudaGetSymbolAddress((void**)&p_cnt_c, g_cnt_c);
    cudaGetSymbolAddress((void**)&p_cnt_d, g_cnt_d);
    cudaGetSymbolAddress((void**)&p_rp_c, g_rp_c);
    cudaGetSymbolAddress((void**)&p_rp_d, g_rp_d);
    cudaGetSymbolAddress((void**)&p_cur_c, g_cur_c);
    cudaGetSymbolAddress((void**)&p_cur_d, g_cur_d);
    cudaGetSymbolAddress((void**)&p_src_c, g_src_c);
    cudaGetSymbolAddress((void**)&p_src_d, g_src_d);

    // ---- CSR build for both edge lists ----
    zero_u32_2<<<(n + 255) / 256, 256>>>(p_cnt_c, p_cnt_d, n);
    hist_kernel<<<2048, 256>>>(ei_conn, ei_dest, E, p_cnt_c, p_cnt_d);
    scan2_kernel<<<2, 1024>>>(p_cnt_c, p_rp_c, p_cur_c, p_cnt_d, p_rp_d, p_cur_d, n);
    fill_kernel<<<2048, 256>>>(ei_conn, ei_dest, E, p_cur_c, p_cur_d, p_src_c, p_src_d);

    // ---- layer 1 (conn, d=8), gather fused ----
    layer1_fused<<<(n + 7) / 8, 256>>>(x, p_rp_c, p_src_c, w_l1, w_r1, b1, p_h1, p_h1h, n);

    // ---- layer 2 (dest, d=128) ----
    gather128h<<<(n * 32 + 255) / 256, 256>>>(p_h1h, p_rp_d, p_src_d, p_agg, n);
    layer23_tc<<<(n + BM - 1) / BM, 256>>>(p_h1, p_agg, w_l2, w_r2, b2, p_h2, p_h2h, n);

    // ---- layer 3 (conn, d=128) ----
    gather128h<<<(n * 32 + 255) / 256, 256>>>(p_h2h, p_rp_c, p_src_c, p_agg, n);
    layer23_tc<<<(n + BM - 1) / BM, 256>>>(p_h2, p_agg, w_l3, w_r3, b3, out, nullptr, n);
}

// round 6
// speedup vs baseline: 1.5545x; 1.0127x over previous
#include <cuda_runtime.h>
#include <cuda_bf16.h>
#include <cuda_fp16.h>
#include <cstdint>

#define N_NODES 100000
#define N_EDGES 1600000
#define HID 128
#define IN_DIM 8

// ---------------- scratch (static __device__, no allocation) ----------------
__device__ float g_h1[(size_t)N_NODES * HID];
__device__ float g_h2[(size_t)N_NODES * HID];
__device__ __half g_h1h[(size_t)N_NODES * HID];
__device__ __half g_h2h[(size_t)N_NODES * HID];
__device__ float g_agg[(size_t)N_NODES * HID];
__device__ int g_cnt_c[N_NODES];
__device__ int g_cnt_d[N_NODES];
__device__ int g_rp_c[N_NODES + 1];
__device__ int g_rp_d[N_NODES + 1];
__device__ int g_cur_c[N_NODES];
__device__ int g_cur_d[N_NODES];
__device__ int g_src_c[N_EDGES];
__device__ int g_src_d[N_EDGES];

// ---------------- CSR build (per-list) ----------------
__global__ void zero1(int* a, int n) {
    int i = blockIdx.x * blockDim.x + threadIdx.x;
    int st = gridDim.x * blockDim.x;
    for (; i < n; i += st) a[i] = 0;
}

__global__ void hist1(const int* __restrict__ ei, int E, int* cnt) {
    int i = blockIdx.x * blockDim.x + threadIdx.x;
    int st = gridDim.x * blockDim.x;
    for (; i < E; i += st) atomicAdd(&cnt[ei[E + i]], 1);
}

__global__ __launch_bounds__(1024) void scan1(const int* __restrict__ cnt,
                                              int* rp, int* cur, int n) {
    __shared__ int s[1024];
    int t = threadIdx.x;
    int per = (n + 1023) / 1024;
    int beg = t * per;
    int end = min(beg + per, n);
    int sum = 0;
    for (int i = beg; i < end; i++) sum += cnt[i];
    s[t] = sum;
    __syncthreads();
    for (int off = 1; off < 1024; off <<= 1) {
        int v = (t >= off) ? s[t - off] : 0;
        __syncthreads();
        s[t] += v;
        __syncthreads();
    }
    int run = s[t] - sum;
    for (int i = beg; i < end; i++) {
        rp[i] = run;
        cur[i] = run;
        run += cnt[i];
    }
    if (t == 1023) rp[n] = s[1023];
}

__global__ void fill1(const int* __restrict__ ei, int E, int* cur,
                      int* __restrict__ srcl) {
    int i = blockIdx.x * blockDim.x + threadIdx.x;
    int st = gridDim.x * blockDim.x;
    for (; i < E; i += st) {
        int s = ei[i], d = ei[E + i];
        srcl[atomicAdd(&cur[d], 1)] = s;
    }
}

// ---------------- gather-mean over fp16 rows, d=128 ----------------
// one warp per node; 16 lanes per 256B row (LDG.128), 2 neighbors/step, 2x unroll
__global__ void gather128h(const __half* __restrict__ h, const int* __restrict__ rp,
                           const int* __restrict__ src, float* __restrict__ out, int n) {
    int node = (blockIdx.x * blockDim.x + threadIdx.x) >> 5;
    int lane = threadIdx.x & 31;
    if (node >= n) return;
    int half = lane >> 4, li = lane & 15;
    int b = __ldg(rp + node), e = __ldg(rp + node + 1);
    float acc[8];
#pragma unroll
    for (int k = 0; k < 8; k++) acc[k] = 0.f;

    int j = b + half;
    for (; j + 2 < e; j += 4) {
        int s0 = __ldg(src + j);
        int s1 = __ldg(src + j + 2);
        uint4 r0 = *(const uint4*)(h + (size_t)s0 * HID + li * 8);
        uint4 r1 = *(const uint4*)(h + (size_t)s1 * HID + li * 8);
#pragma unroll
        for (int q = 0; q < 4; q++) {
            float2 f0 = __half22float2(*(const __half2*)(&r0.x + q));
            float2 f1 = __half22float2(*(const __half2*)(&r1.x + q));
            acc[2 * q]     += f0.x + f1.x;
            acc[2 * q + 1] += f0.y + f1.y;
        }
    }
    if (j < e) {
        int s0 = __ldg(src + j);
        uint4 r0 = *(const uint4*)(h + (size_t)s0 * HID + li * 8);
#pragma unroll
        for (int q = 0; q < 4; q++) {
            float2 f0 = __half22float2(*(const __half2*)(&r0.x + q));
            acc[2 * q]     += f0.x;
            acc[2 * q + 1] += f0.y;
        }
    }
#pragma unroll
    for (int k = 0; k < 8; k++)
        acc[k] += __shfl_xor_sync(0xffffffffu, acc[k], 16);

    if (half == 0) {
        float inv = 1.f / fmaxf((float)(e - b), 1.f);
        float4 o0 = make_float4(acc[0] * inv, acc[1] * inv, acc[2] * inv, acc[3] * inv);
        float4 o1 = make_float4(acc[4] * inv, acc[5] * inv, acc[6] * inv, acc[7] * inv);
        *(float4*)(out + (size_t)node * HID + li * 8) = o0;
        *(float4*)(out + (size_t)node * HID + li * 8 + 4) = o1;
    }
}

// ---------------- layer 1 fused: gather-mean(d=8) + GEMM + norm + tanh ----------------
__global__ void layer1_fused(const float* __restrict__ x,
                             const int* __restrict__ rp, const int* __restrict__ src,
                             const float* __restrict__ wl, const float* __restrict__ wr,
                             const float* __restrict__ bias,
                             float* __restrict__ out, __half* __restrict__ outh, int n) {
    __shared__ float s_wl[IN_DIM * HID];
    __shared__ float s_wr[IN_DIM * HID];
    __shared__ float s_b[HID];
    for (int i = threadIdx.x; i < IN_DIM * HID; i += blockDim.x) {
        s_wl[i] = wl[i];
        s_wr[i] = wr[i];
    }
    if (threadIdx.x < HID) s_b[threadIdx.x] = bias[threadIdx.x];
    __syncthreads();

    int warp = threadIdx.x >> 5, lane = threadIdx.x & 31;
    int node = blockIdx.x * (blockDim.x >> 5) + warp;
    if (node >= n) return;
    int grp = lane >> 3, dim = lane & 7;

    int b = __ldg(rp + node), e = __ldg(rp + node + 1);
    float acc8 = 0.f;
    for (int j = b + grp; j < e; j += 4) {
        int s0 = __ldg(src + j);
        acc8 += __ldg(x + (size_t)s0 * IN_DIM + dim);
    }
    acc8 += __shfl_xor_sync(0xffffffffu, acc8, 8);
    acc8 += __shfl_xor_sync(0xffffffffu, acc8, 16);
    acc8 *= 1.f / fmaxf((float)(e - b), 1.f);

    float my_x = __ldg(x + (size_t)node * IN_DIM + dim);

    float xs[8], as[8];
#pragma unroll
    for (int k = 0; k < 8; k++) {
        xs[k] = __shfl_sync(0xffffffffu, my_x, k);
        as[k] = __shfl_sync(0xffffffffu, acc8, k);
    }
    float acc[4];
#pragma unroll
    for (int c = 0; c < 4; c++) {
        int j = lane + 32 * c;
        float a = s_b[j];
#pragma unroll
        for (int k = 0; k < 8; k++)
            a += as[k] * s_wl[k * HID + j] + xs[k] * s_wr[k * HID + j];
        acc[c] = a;
    }
    float ss = acc[0] * acc[0] + acc[1] * acc[1] + acc[2] * acc[2] + acc[3] * acc[3];
#pragma unroll
    for (int o = 16; o >= 1; o >>= 1) ss += __shfl_xor_sync(0xffffffffu, ss, o);
    float invn = 1.f / fmaxf(sqrtf(ss), 1e-12f);
#pragma unroll
    for (int c = 0; c < 4; c++) {
        float v = tanhf(acc[c] * invn);
        out[(size_t)node * HID + lane + 32 * c] = v;
        outh[(size_t)node * HID + lane + 32 * c] = __float2half(v);
    }
}

// ---------------- bf16-split tensor-core GEMM, layers 2/3 ----------------
#define BM 128
#define BN 128
#define BK 32
#define KW 16
#define LDP 137

__device__ __forceinline__ uint32_t pack_hi(float x0, float x1, float& r0, float& r1) {
    __nv_bfloat162 h = __floats2bfloat162_rn(x0, x1);
    r0 = x0 - __bfloat162float(h.x);
    r1 = x1 - __bfloat162float(h.y);
    return *(uint32_t*)&h;
}
__device__ __forceinline__ uint32_t pack_lo(float r0, float r1) {
    __nv_bfloat162 l = __floats2bfloat162_rn(r0, r1);
    return *(uint32_t*)&l;
}

__device__ __forceinline__ void mma_bf16(float* c, uint32_t a0, uint32_t a1,
                                         uint32_t a2, uint32_t a3,
                                         uint32_t b0, uint32_t b1) {
    asm volatile(
        "mma.sync.aligned.m16n8k16.row.col.f32.bf16.bf16.f32 "
        "{%0,%1,%2,%3}, {%4,%5,%6,%7}, {%8,%9}, {%0,%1,%2,%3};"
        : "+f"(c[0]), "+f"(c[1]), "+f"(c[2]), "+f"(c[3])
        : "r"(a0), "r"(a1), "r"(a2), "r"(a3), "r"(b0), "r"(b1));
}

__global__ __launch_bounds__(256, 2) void layer23_tc(
    const float* __restrict__ hin, const float* __restrict__ mean,
    const float* __restrict__ wl, const float* __restrict__ wr,
    const float* __restrict__ bias, float* __restrict__ out,
    __half* __restrict__ outh, int n) {
    __shared__ uint32_t Ah[KW * LDP];
    __shared__ uint32_t Al[KW * LDP];
    __shared__ uint32_t Bh[KW * LDP];
    __shared__ uint32_t Bl[KW * LDP];
    __shared__ float ss_part[2 * BM];

    int t = threadIdx.x;
    int row0 = blockIdx.x * BM;
    int wid = t >> 5, lane = t & 31;
    int warp_m = wid & 3;
    int warp_n = wid >> 2;
    int g = lane >> 2, tig = lane & 3;

    float acc[2][8][4];
#pragma unroll
    for (int i = 0; i < 2; i++)
#pragma unroll
        for (int j = 0; j < 8; j++)
#pragma unroll
            for (int c = 0; c < 4; c++) acc[i][j][c] = 0.f;

    for (int kc = 0; kc < 256; kc += BK) {
        const float* abase = (kc < 128) ? mean : hin;
        int koff = (kc < 128) ? kc : kc - 128;
#pragma unroll
        for (int r = 0; r < 4; r++) {
            int f = t + r * 256;
            int m = f >> 3, kq = f & 7;
            int gi = row0 + m;
            int ic = gi < n ? gi : n - 1;
            float4 v = *(const float4*)(abase + (size_t)ic * HID + koff + kq * 4);
            float r0, r1, r2, r3;
            uint32_t h0 = pack_hi(v.x, v.y, r0, r1);
            uint32_t h1 = pack_hi(v.z, v.w, r2, r3);
            Ah[(2 * kq) * LDP + m] = h0;
            Ah[(2 * kq + 1) * LDP + m] = h1;
            Al[(2 * kq) * LDP + m] = pack_lo(r0, r1);
            Al[(2 * kq + 1) * LDP + m] = pack_lo(r2, r3);
        }
        const float* wbase = (kc < 128) ? wl : wr;
        int wkoff = (kc < 128) ? kc : kc - 128;
#pragma unroll
        for (int r = 0; r < 2; r++) {
            int f = t + r * 256;
            int kk = f >> 5, q = f & 31;
            const float* w0 = wbase + (size_t)(wkoff + 2 * kk) * HID + q * 4;
            const float* w1 = w0 + HID;
            float4 va = *(const float4*)w0;
            float4 vb = *(const float4*)w1;
            float r0, r1;
#pragma unroll
            for (int j = 0; j < 4; j++) {
                uint32_t h = pack_hi((&va.x)[j], (&vb.x)[j], r0, r1);
                Bh[kk * LDP + q * 4 + j] = h;
                Bl[kk * LDP + q * 4 + j] = pack_lo(r0, r1);
            }
        }
        __syncthreads();

#pragma unroll
        for (int s = 0; s < 2; s++) {
            int k0 = s * 8;
            uint32_t ah[2][4], al[2][4];
#pragma unroll
            for (int mi = 0; mi < 2; mi++) {
                int m0 = warp_m * 32 + mi * 16;
                ah[mi][0] = Ah[(k0 + tig) * LDP + m0 + g];
                ah[mi][1] = Ah[(k0 + tig) * LDP + m0 + g + 8];
                ah[mi][2] = Ah[(k0 + tig + 4) * LDP + m0 + g];
                ah[mi][3] = Ah[(k0 + tig + 4) * LDP + m0 + g + 8];
                al[mi][0] = Al[(k0 + tig) * LDP + m0 + g];
                al[mi][1] = Al[(k0 + tig) * LDP + m0 + g + 8];
                al[mi][2] = Al[(k0 + tig + 4) * LDP + m0 + g];
                al[mi][3] = Al[(k0 + tig + 4) * LDP + m0 + g + 8];
            }
#pragma unroll
            for (int nt = 0; nt < 8; nt++) {
                int n0 = warp_n * 64 + nt * 8;
                uint32_t bh0 = Bh[(k0 + tig) * LDP + n0 + g];
                uint32_t bh1 = Bh[(k0 + tig + 4) * LDP + n0 + g];
                uint32_t bl0 = Bl[(k0 + tig) * LDP + n0 + g];
                uint32_t bl1 = Bl[(k0 + tig + 4) * LDP + n0 + g];
#pragma unroll
                for (int mi = 0; mi < 2; mi++) {
                    mma_bf16(acc[mi][nt], ah[mi][0], ah[mi][1], ah[mi][2], ah[mi][3], bh0, bh1);
                    mma_bf16(acc[mi][nt], ah[mi][0], ah[mi][1], ah[mi][2], ah[mi][3], bl0, bl1);
                    mma_bf16(acc[mi][nt], al[mi][0], al[mi][1], al[mi][2], al[mi][3], bh0, bh1);
                }
            }
        }
        __syncthreads();
    }

    float2 bv[8];
#pragma unroll
    for (int nt = 0; nt < 8; nt++)
        bv[nt] = *(const float2*)(bias + warp_n * 64 + nt * 8 + 2 * tig);

#pragma unroll
    for (int mi = 0; mi < 2; mi++) {
#pragma unroll
        for (int h = 0; h < 2; h++) {
            float ss = 0.f;
#pragma unroll
            for (int nt = 0; nt < 8; nt++) {
                acc[mi][nt][2 * h]     += bv[nt].x;
                acc[mi][nt][2 * h + 1] += bv[nt].y;
                ss += acc[mi][nt][2 * h] * acc[mi][nt][2 * h]
                    + acc[mi][nt][2 * h + 1] * acc[mi][nt][2 * h + 1];
            }
            ss += __shfl_xor_sync(0xffffffffu, ss, 1);
            ss += __shfl_xor_sync(0xffffffffu, ss, 2);
            if (tig == 0)
                ss_part[warp_n * BM + warp_m * 32 + mi * 16 + h * 8 + g] = ss;
        }
    }
    __syncthreads();

#pragma unroll
    for (int mi = 0; mi < 2; mi++) {
#pragma unroll
        for (int h = 0; h < 2; h++) {
            int rloc = warp_m * 32 + mi * 16 + h * 8 + g;
            int gi = row0 + rloc;
            if (gi >= n) continue;
            float tot = ss_part[rloc] + ss_part[BM + rloc];
            float invn = 1.f / fmaxf(sqrtf(tot), 1e-12f);
#pragma unroll
            for (int nt = 0; nt < 8; nt++) {
                float2 o;
                o.x = tanhf(acc[mi][nt][2 * h] * invn);
                o.y = tanhf(acc[mi][nt][2 * h + 1] * invn);
                size_t off = (size_t)gi * HID + warp_n * 64 + nt * 8 + 2 * tig;
                *(float2*)(out + off) = o;
                if (outh) *(__half2*)(outh + off) = __floats2half2_rn(o.x, o.y);
            }
        }
    }
}

// ---------------- launch ----------------
extern "C" void kernel_launch(void* const* d_in, const int* in_sizes, int n_in,
                              void* d_out, int out_size) {
    const float* x       = (const float*)d_in[0];
    const int*   ei_conn = (const int*)d_in[1];
    const int*   ei_dest = (const int*)d_in[2];
    const float* w_l1 = (const float*)d_in[3];
    const float* w_r1 = (const float*)d_in[4];
    const float* b1   = (const float*)d_in[5];
    const float* w_l2 = (const float*)d_in[6];
    const float* w_r2 = (const float*)d_in[7];
    const float* b2   = (const float*)d_in[8];
    const float* w_l3 = (const float*)d_in[9];
    const float* w_r3 = (const float*)d_in[10];
    const float* b3   = (const float*)d_in[11];
    float* out = (float*)d_out;

    const int n = N_NODES;
    const int E = in_sizes[1] / 2;

    float *p_h1, *p_h2, *p_agg;
    __half *p_h1h, *p_h2h;
    int *p_cnt_c, *p_cnt_d, *p_rp_c, *p_rp_d, *p_cur_c, *p_cur_d, *p_src_c, *p_src_d;
    cudaGetSymbolAddress((void**)&p_h1, g_h1);
    cudaGetSymbolAddress((void**)&p_h2, g_h2);
    cudaGetSymbolAddress((void**)&p_h1h, g_h1h);
    cudaGetSymbolAddress((void**)&p_h2h, g_h2h);
    cudaGetSymbolAddress((void**)&p_agg, g_agg);
    cudaGetSymbolAddress((void**)&p_cnt_c, g_cnt_c);
    cudaGetSymbolAddress((void**)&p_cnt_d, g_cnt_d);
    cudaGetSymbolAddress((void**)&p_rp_c, g_rp_c);
    cudaGetSymbolAddress((void**)&p_rp_d, g_rp_d);
    cudaGetSymbolAddress((void**)&p_cur_c, g_cur_c);
    cudaGetSymbolAddress((void**)&p_cur_d, g_cur_d);
    cudaGetSymbolAddress((void**)&p_src_c, g_src_c);
    cudaGetSymbolAddress((void**)&p_src_d, g_src_d);

    // persistent side stream + fork/join events (created once; handles only)
    static cudaStream_t sB = nullptr;
    static cudaEvent_t evFork = nullptr, evJoin = nullptr;
    if (!sB) {
        cudaStreamCreateWithFlags(&sB, cudaStreamNonBlocking);
        cudaEventCreateWithFlags(&evFork, cudaEventDisableTiming);
        cudaEventCreateWithFlags(&evJoin, cudaEventDisableTiming);
    }

    // ---- fork: build dest-list CSR on side stream ----
    cudaEventRecord(evFork, 0);
    cudaStreamWaitEvent(sB, evFork, 0);
    zero1<<<(n + 255) / 256, 256, 0, sB>>>(p_cnt_d, n);
    hist1<<<1024, 256, 0, sB>>>(ei_dest, E, p_cnt_d);
    scan1<<<1, 1024, 0, sB>>>(p_cnt_d, p_rp_d, p_cur_d, n);
    fill1<<<1024, 256, 0, sB>>>(ei_dest, E, p_cur_d, p_src_d);
    cudaEventRecord(evJoin, sB);

    // ---- main stream: conn-list CSR + layer 1 ----
    zero1<<<(n + 255) / 256, 256>>>(p_cnt_c, n);
    hist1<<<1024, 256>>>(ei_conn, E, p_cnt_c);
    scan1<<<1, 1024>>>(p_cnt_c, p_rp_c, p_cur_c, n);
    fill1<<<1024, 256>>>(ei_conn, E, p_cur_c, p_src_c);
    layer1_fused<<<(n + 7) / 8, 256>>>(x, p_rp_c, p_src_c, w_l1, w_r1, b1, p_h1, p_h1h, n);

    // ---- join, then layer 2 (dest) ----
    cudaStreamWaitEvent(0, evJoin, 0);
    gather128h<<<(n * 32 + 255) / 256, 256>>>(p_h1h, p_rp_d, p_src_d, p_agg, n);
    layer23_tc<<<(n + BM - 1) / BM, 256>>>(p_h1, p_agg, w_l2, w_r2, b2, p_h2, p_h2h, n);

    // ---- layer 3 (conn) ----
    gather128h<<<(n * 32 + 255) / 256, 256>>>(p_h2h, p_rp_c, p_src_c, p_agg, n);
    layer23_tc<<<(n + BM - 1) / BM, 256>>>(p_h2, p_agg, w_l3, w_r3, b3, out, nullptr, n);
}

// round 8
// speedup vs baseline: 1.5859x; 1.0202x over previous
#include <cuda_runtime.h>
#include <cuda_bf16.h>
#include <cuda_fp16.h>
#include <cstdint>

#define N_NODES 100000
#define N_EDGES 1600000
#define HID 128
#define IN_DIM 8

// ---------------- scratch (static __device__, no allocation) ----------------
__device__ __half g_h1h[(size_t)N_NODES * HID];
__device__ __half g_h2h[(size_t)N_NODES * HID];
__device__ __half g_aggh[(size_t)N_NODES * HID];
__device__ int g_cnt_c[N_NODES];
__device__ int g_cnt_d[N_NODES];
__device__ int g_rp_c[N_NODES + 1];
__device__ int g_rp_d[N_NODES + 1];
__device__ int g_cur_c[N_NODES];
__device__ int g_cur_d[N_NODES];
__device__ int g_src_c[N_EDGES];
__device__ int g_src_d[N_EDGES];

// ---------------- CSR build (per-list) ----------------
__global__ void zero1(int* a, int n) {
    int i = blockIdx.x * blockDim.x + threadIdx.x;
    int st = gridDim.x * blockDim.x;
    for (; i < n; i += st) a[i] = 0;
}
__global__ void hist1(const int* __restrict__ ei, int E, int* cnt) {
    int i = blockIdx.x * blockDim.x + threadIdx.x;
    int st = gridDim.x * blockDim.x;
    for (; i < E; i += st) atomicAdd(&cnt[ei[E + i]], 1);
}
__global__ __launch_bounds__(1024) void scan1(const int* __restrict__ cnt,
                                              int* rp, int* cur, int n) {
    __shared__ int s[1024];
    int t = threadIdx.x;
    int per = (n + 1023) / 1024;
    int beg = t * per;
    int end = min(beg + per, n);
    int sum = 0;
    for (int i = beg; i < end; i++) sum += cnt[i];
    s[t] = sum;
    __syncthreads();
    for (int off = 1; off < 1024; off <<= 1) {
        int v = (t >= off) ? s[t - off] : 0;
        __syncthreads();
        s[t] += v;
        __syncthreads();
    }
    int run = s[t] - sum;
    for (int i = beg; i < end; i++) {
        rp[i] = run;
        cur[i] = run;
        run += cnt[i];
    }
    if (t == 1023) rp[n] = s[1023];
}
__global__ void fill1(const int* __restrict__ ei, int E, int* cur,
                      int* __restrict__ srcl) {
    int i = blockIdx.x * blockDim.x + threadIdx.x;
    int st = gridDim.x * blockDim.x;
    for (; i < E; i += st) {
        int s = ei[i], d = ei[E + i];
        srcl[atomicAdd(&cur[d], 1)] = s;
    }
}

// ---------------- gather-mean over fp16 rows -> fp16 mean, d=128 ----------------
__global__ void gather128h(const __half* __restrict__ h, const int* __restrict__ rp,
                           const int* __restrict__ src, __half* __restrict__ outh, int n) {
    int node = (blockIdx.x * blockDim.x + threadIdx.x) >> 5;
    int lane = threadIdx.x & 31;
    if (node >= n) return;
    int half = lane >> 4, li = lane & 15;
    int b = __ldg(rp + node), e = __ldg(rp + node + 1);
    float acc[8];
#pragma unroll
    for (int k = 0; k < 8; k++) acc[k] = 0.f;

    int j = b + half;
    for (; j + 2 < e; j += 4) {
        int s0 = __ldg(src + j);
        int s1 = __ldg(src + j + 2);
        uint4 r0 = *(const uint4*)(h + (size_t)s0 * HID + li * 8);
        uint4 r1 = *(const uint4*)(h + (size_t)s1 * HID + li * 8);
#pragma unroll
        for (int q = 0; q < 4; q++) {
            float2 f0 = __half22float2(*(const __half2*)(&r0.x + q));
            float2 f1 = __half22float2(*(const __half2*)(&r1.x + q));
            acc[2 * q]     += f0.x + f1.x;
            acc[2 * q + 1] += f0.y + f1.y;
        }
    }
    if (j < e) {
        int s0 = __ldg(src + j);
        uint4 r0 = *(const uint4*)(h + (size_t)s0 * HID + li * 8);
#pragma unroll
        for (int q = 0; q < 4; q++) {
            float2 f0 = __half22float2(*(const __half2*)(&r0.x + q));
            acc[2 * q]     += f0.x;
            acc[2 * q + 1] += f0.y;
        }
    }
#pragma unroll
    for (int k = 0; k < 8; k++)
        acc[k] += __shfl_xor_sync(0xffffffffu, acc[k], 16);

    if (half == 0) {
        float inv = 1.f / fmaxf((float)(e - b), 1.f);
        uint4 o;
        ((__half2*)&o)[0] = __floats2half2_rn(acc[0] * inv, acc[1] * inv);
        ((__half2*)&o)[1] = __floats2half2_rn(acc[2] * inv, acc[3] * inv);
        ((__half2*)&o)[2] = __floats2half2_rn(acc[4] * inv, acc[5] * inv);
        ((__half2*)&o)[3] = __floats2half2_rn(acc[6] * inv, acc[7] * inv);
        *(uint4*)(outh + (size_t)node * HID + li * 8) = o;
    }
}

// ---------------- layer 1 fused: gather-mean(d=8) + GEMM + norm + tanh ----------------
__global__ void layer1_fused(const float* __restrict__ x,
                             const int* __restrict__ rp, const int* __restrict__ src,
                             const float* __restrict__ wl, const float* __restrict__ wr,
                             const float* __restrict__ bias,
                             __half* __restrict__ outh, int n) {
    __shared__ float s_wl[IN_DIM * HID];
    __shared__ float s_wr[IN_DIM * HID];
    __shared__ float s_b[HID];
    for (int i = threadIdx.x; i < IN_DIM * HID; i += blockDim.x) {
        s_wl[i] = wl[i];
        s_wr[i] = wr[i];
    }
    if (threadIdx.x < HID) s_b[threadIdx.x] = bias[threadIdx.x];
    __syncthreads();

    int warp = threadIdx.x >> 5, lane = threadIdx.x & 31;
    int node = blockIdx.x * (blockDim.x >> 5) + warp;
    if (node >= n) return;
    int grp = lane >> 3, dim = lane & 7;

    int b = __ldg(rp + node), e = __ldg(rp + node + 1);
    float acc8 = 0.f;
    for (int j = b + grp; j < e; j += 4) {
        int s0 = __ldg(src + j);
        acc8 += __ldg(x + (size_t)s0 * IN_DIM + dim);
    }
    acc8 += __shfl_xor_sync(0xffffffffu, acc8, 8);
    acc8 += __shfl_xor_sync(0xffffffffu, acc8, 16);
    acc8 *= 1.f / fmaxf((float)(e - b), 1.f);

    float my_x = __ldg(x + (size_t)node * IN_DIM + dim);

    float xs[8], as[8];
#pragma unroll
    for (int k = 0; k < 8; k++) {
        xs[k] = __shfl_sync(0xffffffffu, my_x, k);
        as[k] = __shfl_sync(0xffffffffu, acc8, k);
    }
    float acc[4];
#pragma unroll
    for (int c = 0; c < 4; c++) {
        int j = lane + 32 * c;
        float a = s_b[j];
#pragma unroll
        for (int k = 0; k < 8; k++)
            a += as[k] * s_wl[k * HID + j] + xs[k] * s_wr[k * HID + j];
        acc[c] = a;
    }
    float ss = acc[0] * acc[0] + acc[1] * acc[1] + acc[2] * acc[2] + acc[3] * acc[3];
#pragma unroll
    for (int o = 16; o >= 1; o >>= 1) ss += __shfl_xor_sync(0xffffffffu, ss, o);
    float invn = 1.f / fmaxf(sqrtf(ss), 1e-12f);
#pragma unroll
    for (int c = 0; c < 4; c++) {
        float v = tanhf(acc[c] * invn);
        outh[(size_t)node * HID + lane + 32 * c] = __float2half(v);
    }
}

// ---------------- bf16-split tensor-core GEMM, layers 2/3 ----------------
// A read from fp16 arrays (mean, hin); bf16 hi/lo split is exact on fp16 values.
#define BM 128
#define BN 128
#define BK 32
#define KW 16
#define LDP 137

__device__ __forceinline__ uint32_t pack_hi(float x0, float x1, float& r0, float& r1) {
    __nv_bfloat162 h = __floats2bfloat162_rn(x0, x1);
    r0 = x0 - __bfloat162float(h.x);
    r1 = x1 - __bfloat162float(h.y);
    return *(uint32_t*)&h;
}
__device__ __forceinline__ uint32_t pack_lo(float r0, float r1) {
    __nv_bfloat162 l = __floats2bfloat162_rn(r0, r1);
    return *(uint32_t*)&l;
}

__device__ __forceinline__ void mma_bf16(float* c, uint32_t a0, uint32_t a1,
                                         uint32_t a2, uint32_t a3,
                                         uint32_t b0, uint32_t b1) {
    asm volatile(
        "mma.sync.aligned.m16n8k16.row.col.f32.bf16.bf16.f32 "
        "{%0,%1,%2,%3}, {%4,%5,%6,%7}, {%8,%9}, {%0,%1,%2,%3};"
        : "+f"(c[0]), "+f"(c[1]), "+f"(c[2]), "+f"(c[3])
        : "r"(a0), "r"(a1), "r"(a2), "r"(a3), "r"(b0), "r"(b1));
}

__global__ __launch_bounds__(256, 2) void layer23_tc(
    const __half* __restrict__ hinh, const __half* __restrict__ meanh,
    const float* __restrict__ wl, const float* __restrict__ wr,
    const float* __restrict__ bias, float* __restrict__ out,
    __half* __restrict__ outh, int n) {
    __shared__ uint32_t Ah[KW * LDP];
    __shared__ uint32_t Al[KW * LDP];
    __shared__ uint32_t Bh[KW * LDP];
    __shared__ uint32_t Bl[KW * LDP];
    __shared__ float ss_part[2 * BM];

    int t = threadIdx.x;
    int row0 = blockIdx.x * BM;
    int wid = t >> 5, lane = t & 31;
    int warp_m = wid & 3;
    int warp_n = wid >> 2;
    int g = lane >> 2, tig = lane & 3;

    float acc[2][8][4];
#pragma unroll
    for (int i = 0; i < 2; i++)
#pragma unroll
        for (int j = 0; j < 8; j++)
#pragma unroll
            for (int c = 0; c < 4; c++) acc[i][j][c] = 0.f;

    for (int kc = 0; kc < 256; kc += BK) {
        const __half* abase = (kc < 128) ? meanh : hinh;
        int koff = (kc < 128) ? kc : kc - 128;
#pragma unroll
        for (int r = 0; r < 4; r++) {
            int f = t + r * 256;
            int m = f >> 3, kq = f & 7;
            int gi = row0 + m;
            int ic = gi < n ? gi : n - 1;
            uint2 rv = *(const uint2*)(abase + (size_t)ic * HID + koff + kq * 4);
            float2 f01 = __half22float2(*(const __half2*)&rv.x);
            float2 f23 = __half22float2(*(const __half2*)&rv.y);
            float r0, r1, r2, r3;
            uint32_t h0 = pack_hi(f01.x, f01.y, r0, r1);
            uint32_t h1 = pack_hi(f23.x, f23.y, r2, r3);
            Ah[(2 * kq) * LDP + m] = h0;
            Ah[(2 * kq + 1) * LDP + m] = h1;
            Al[(2 * kq) * LDP + m] = pack_lo(r0, r1);
            Al[(2 * kq + 1) * LDP + m] = pack_lo(r2, r3);
        }
        const float* wbase = (kc < 128) ? wl : wr;
        int wkoff = (kc < 128) ? kc : kc - 128;
#pragma unroll
        for (int r = 0; r < 2; r++) {
            int f = t + r * 256;
            int kk = f >> 5, q = f & 31;
            const float* w0 = wbase + (size_t)(wkoff + 2 * kk) * HID + q * 4;
            const float* w1 = w0 + HID;
            float4 va = *(const float4*)w0;
            float4 vb = *(const float4*)w1;
            float r0, r1;
#pragma unroll
            for (int j = 0; j < 4; j++) {
                uint32_t h = pack_hi((&va.x)[j], (&vb.x)[j], r0, r1);
                Bh[kk * LDP + q * 4 + j] = h;
                Bl[kk * LDP + q * 4 + j] = pack_lo(r0, r1);
            }
        }
        __syncthreads();

#pragma unroll
        for (int s = 0; s < 2; s++) {
            int k0 = s * 8;
            uint32_t ah[2][4], al[2][4];
#pragma unroll
            for (int mi = 0; mi < 2; mi++) {
                int m0 = warp_m * 32 + mi * 16;
                ah[mi][0] = Ah[(k0 + tig) * LDP + m0 + g];
                ah[mi][1] = Ah[(k0 + tig) * LDP + m0 + g + 8];
                ah[mi][2] = Ah[(k0 + tig + 4) * LDP + m0 + g];
                ah[mi][3] = Ah[(k0 + tig + 4) * LDP + m0 + g + 8];
                al[mi][0] = Al[(k0 + tig) * LDP + m0 + g];
                al[mi][1] = Al[(k0 + tig) * LDP + m0 + g + 8];
                al[mi][2] = Al[(k0 + tig + 4) * LDP + m0 + g];
                al[mi][3] = Al[(k0 + tig + 4) * LDP + m0 + g + 8];
            }
#pragma unroll
            for (int nt = 0; nt < 8; nt++) {
                int n0 = warp_n * 64 + nt * 8;
                uint32_t bh0 = Bh[(k0 + tig) * LDP + n0 + g];
                uint32_t bh1 = Bh[(k0 + tig + 4) * LDP + n0 + g];
                uint32_t bl0 = Bl[(k0 + tig) * LDP + n0 + g];
                uint32_t bl1 = Bl[(k0 + tig + 4) * LDP + n0 + g];
#pragma unroll
                for (int mi = 0; mi < 2; mi++) {
                    mma_bf16(acc[mi][nt], ah[mi][0], ah[mi][1], ah[mi][2], ah[mi][3], bh0, bh1);
                    mma_bf16(acc[mi][nt], ah[mi][0], ah[mi][1], ah[mi][2], ah[mi][3], bl0, bl1);
                    mma_bf16(acc[mi][nt], al[mi][0], al[mi][1], al[mi][2], al[mi][3], bh0, bh1);
                }
            }
        }
        __syncthreads();
    }

    float2 bv[8];
#pragma unroll
    for (int nt = 0; nt < 8; nt++)
        bv[nt] = *(const float2*)(bias + warp_n * 64 + nt * 8 + 2 * tig);

#pragma unroll
    for (int mi = 0; mi < 2; mi++) {
#pragma unroll
        for (int h = 0; h < 2; h++) {
            float ss = 0.f;
#pragma unroll
            for (int nt = 0; nt < 8; nt++) {
                acc[mi][nt][2 * h]     += bv[nt].x;
                acc[mi][nt][2 * h + 1] += bv[nt].y;
                ss += acc[mi][nt][2 * h] * acc[mi][nt][2 * h]
                    + acc[mi][nt][2 * h + 1] * acc[mi][nt][2 * h + 1];
            }
            ss += __shfl_xor_sync(0xffffffffu, ss, 1);
            ss += __shfl_xor_sync(0xffffffffu, ss, 2);
            if (tig == 0)
                ss_part[warp_n * BM + warp_m * 32 + mi * 16 + h * 8 + g] = ss;
        }
    }
    __syncthreads();

#pragma unroll
    for (int mi = 0; mi < 2; mi++) {
#pragma unroll
        for (int h = 0; h < 2; h++) {
            int rloc = warp_m * 32 + mi * 16 + h * 8 + g;
            int gi = row0 + rloc;
            if (gi >= n) continue;
            float tot = ss_part[rloc] + ss_part[BM + rloc];
            float invn = 1.f / fmaxf(sqrtf(tot), 1e-12f);
#pragma unroll
            for (int nt = 0; nt < 8; nt++) {
                float2 o;
                o.x = tanhf(acc[mi][nt][2 * h] * invn);
                o.y = tanhf(acc[mi][nt][2 * h + 1] * invn);
                size_t off = (size_t)gi * HID + warp_n * 64 + nt * 8 + 2 * tig;
                if (out) *(float2*)(out + off) = o;
                if (outh) *(__half2*)(outh + off) = __floats2half2_rn(o.x, o.y);
            }
        }
    }
}

// ---------------- launch ----------------
extern "C" void kernel_launch(void* const* d_in, const int* in_sizes, int n_in,
                              void* d_out, int out_size) {
    const float* x       = (const float*)d_in[0];
    const int*   ei_conn = (const int*)d_in[1];
    const int*   ei_dest = (const int*)d_in[2];
    const float* w_l1 = (const float*)d_in[3];
    const float* w_r1 = (const float*)d_in[4];
    const float* b1   = (const float*)d_in[5];
    const float* w_l2 = (const float*)d_in[6];
    const float* w_r2 = (const float*)d_in[7];
    const float* b2   = (const float*)d_in[8];
    const float* w_l3 = (const float*)d_in[9];
    const float* w_r3 = (const float*)d_in[10];
    const float* b3   = (const float*)d_in[11];
    float* out = (float*)d_out;

    const int n = N_NODES;
    const int E = in_sizes[1] / 2;

    __half *p_h1h, *p_h2h, *p_aggh;
    int *p_cnt_c, *p_cnt_d, *p_rp_c, *p_rp_d, *p_cur_c, *p_cur_d, *p_src_c, *p_src_d;
    cudaGetSymbolAddress((void**)&p_h1h, g_h1h);
    cudaGetSymbolAddress((void**)&p_h2h, g_h2h);
    cudaGetSymbolAddress((void**)&p_aggh, g_aggh);
    cudaGetSymbolAddress((void**)&p_cnt_c, g_cnt_c);
    cudaGetSymbolAddress((void**)&p_cnt_d, g_cnt_d);
    cudaGetSymbolAddress((void**)&p_rp_c, g_rp_c);
    cudaGetSymbolAddress((void**)&p_rp_d, g_rp_d);
    cudaGetSymbolAddress((void**)&p_cur_c, g_cur_c);
    cudaGetSymbolAddress((void**)&p_cur_d, g_cur_d);
    cudaGetSymbolAddress((void**)&p_src_c, g_src_c);
    cudaGetSymbolAddress((void**)&p_src_d, g_src_d);

    static cudaStream_t sB = nullptr;
    static cudaEvent_t evFork = nullptr, evJoin = nullptr;
    if (!sB) {
        cudaStreamCreateWithFlags(&sB, cudaStreamNonBlocking);
        cudaEventCreateWithFlags(&evFork, cudaEventDisableTiming);
        cudaEventCreateWithFlags(&evJoin, cudaEventDisableTiming);
    }

    // ---- fork: build dest-list CSR on side stream ----
    cudaEventRecord(evFork, 0);
    cudaStreamWaitEvent(sB, evFork, 0);
    zero1<<<(n + 255) / 256, 256, 0, sB>>>(p_cnt_d, n);
    hist1<<<1024, 256, 0, sB>>>(ei_dest, E, p_cnt_d);
    scan1<<<1, 1024, 0, sB>>>(p_cnt_d, p_rp_d, p_cur_d, n);
    fill1<<<1024, 256, 0, sB>>>(ei_dest, E, p_cur_d, p_src_d);
    cudaEventRecord(evJoin, sB);

    // ---- main stream: conn-list CSR + layer 1 ----
    zero1<<<(n + 255) / 256, 256>>>(p_cnt_c, n);
    hist1<<<1024, 256>>>(ei_conn, E, p_cnt_c);
    scan1<<<1, 1024>>>(p_cnt_c, p_rp_c, p_cur_c, n);
    fill1<<<1024, 256>>>(ei_conn, E, p_cur_c, p_src_c);
    layer1_fused<<<(n + 7) / 8, 256>>>(x, p_rp_c, p_src_c, w_l1, w_r1, b1, p_h1h, n);

    // ---- join, then layer 2 (dest) ----
    cudaStreamWaitEvent(0, evJoin, 0);
    gather128h<<<(n * 32 + 255) / 256, 256>>>(p_h1h, p_rp_d, p_src_d, p_aggh, n);
    layer23_tc<<<(n + BM - 1) / BM, 256>>>(p_h1h, p_aggh, w_l2, w_r2, b2,
                                           nullptr, p_h2h, n);

    // ---- layer 3 (conn) ----
    gather128h<<<(n * 32 + 255) / 256, 256>>>(p_h2h, p_rp_c, p_src_c, p_aggh, n);
    layer23_tc<<<(n + BM - 1) / BM, 256>>>(p_h2h, p_aggh, w_l3, w_r3, b3,
                                           out, nullptr, n);
}

// round 9
// speedup vs baseline: 1.7551x; 1.1067x over previous
#include <cuda_runtime.h>
#include <cuda_fp16.h>
#include <cstdint>

#define N_NODES 100000
#define N_EDGES 1600000
#define HID 128
#define IN_DIM 8

// ---------------- scratch (static __device__, no allocation) ----------------
__device__ __half g_h1h[(size_t)N_NODES * HID];
__device__ __half g_h2h[(size_t)N_NODES * HID];
__device__ __half g_aggh[(size_t)N_NODES * HID];
__device__ __half g_wt2h[128 * 256];
__device__ __half g_wt2l[128 * 256];
__device__ __half g_wt3h[128 * 256];
__device__ __half g_wt3l[128 * 256];
__device__ int g_cnt_c[N_NODES];
__device__ int g_cnt_d[N_NODES];
__device__ int g_rp_c[N_NODES + 1];
__device__ int g_rp_d[N_NODES + 1];
__device__ int g_cur_c[N_NODES];
__device__ int g_cur_d[N_NODES];
__device__ int g_src_c[N_EDGES];
__device__ int g_src_d[N_EDGES];

// ---------------- CSR build (per-list) ----------------
__global__ void zero1(int* a, int n) {
    int i = blockIdx.x * blockDim.x + threadIdx.x;
    int st = gridDim.x * blockDim.x;
    for (; i < n; i += st) a[i] = 0;
}
__global__ void hist1(const int* __restrict__ ei, int E, int* cnt) {
    int i = blockIdx.x * blockDim.x + threadIdx.x;
    int st = gridDim.x * blockDim.x;
    for (; i < E; i += st) atomicAdd(&cnt[ei[E + i]], 1);
}
__global__ __launch_bounds__(1024) void scan1(const int* __restrict__ cnt,
                                              int* rp, int* cur, int n) {
    __shared__ int s[1024];
    int t = threadIdx.x;
    int per = (n + 1023) / 1024;
    int beg = t * per;
    int end = min(beg + per, n);
    int sum = 0;
    for (int i = beg; i < end; i++) sum += cnt[i];
    s[t] = sum;
    __syncthreads();
    for (int off = 1; off < 1024; off <<= 1) {
        int v = (t >= off) ? s[t - off] : 0;
        __syncthreads();
        s[t] += v;
        __syncthreads();
    }
    int run = s[t] - sum;
    for (int i = beg; i < end; i++) {
        rp[i] = run;
        cur[i] = run;
        run += cnt[i];
    }
    if (t == 1023) rp[n] = s[1023];
}
__global__ void fill1(const int* __restrict__ ei, int E, int* cur,
                      int* __restrict__ srcl) {
    int i = blockIdx.x * blockDim.x + threadIdx.x;
    int st = gridDim.x * blockDim.x;
    for (; i < E; i += st) {
        int s = ei[i], d = ei[E + i];
        srcl[atomicAdd(&cur[d], 1)] = s;
    }
}

// ---------------- weight prep: W[k][n] fp32 -> Wt[n][256] fp16 hi/lo ----------------
__global__ void wprep(const float* __restrict__ wl2, const float* __restrict__ wr2,
                      const float* __restrict__ wl3, const float* __restrict__ wr3,
                      __half* w2h, __half* w2l, __half* w3h, __half* w3l) {
    int i = blockIdx.x * blockDim.x + threadIdx.x;
    if (i >= 2 * 128 * 256) return;
    int layer = i >> 15;
    int rem = i & 32767;
    int nrow = rem >> 8, k = rem & 255;
    const float* wlm = layer ? wl3 : wl2;
    const float* wrm = layer ? wr3 : wr2;
    float v = (k < 128) ? wlm[k * 128 + nrow] : wrm[(k - 128) * 128 + nrow];
    __half h = __float2half(v);
    __half l = __float2half(v - __half2float(h));
    (layer ? w3h : w2h)[nrow * 256 + k] = h;
    (layer ? w3l : w2l)[nrow * 256 + k] = l;
}

// ---------------- gather-mean over fp16 rows -> fp16 mean, d=128 ----------------
__global__ void gather128h(const __half* __restrict__ h, const int* __restrict__ rp,
                           const int* __restrict__ src, __half* __restrict__ outh, int n) {
    int node = (blockIdx.x * blockDim.x + threadIdx.x) >> 5;
    int lane = threadIdx.x & 31;
    if (node >= n) return;
    int half = lane >> 4, li = lane & 15;
    int b = __ldg(rp + node), e = __ldg(rp + node + 1);
    float acc[8];
#pragma unroll
    for (int k = 0; k < 8; k++) acc[k] = 0.f;

    int j = b + half;
    for (; j + 2 < e; j += 4) {
        int s0 = __ldg(src + j);
        int s1 = __ldg(src + j + 2);
        uint4 r0 = *(const uint4*)(h + (size_t)s0 * HID + li * 8);
        uint4 r1 = *(const uint4*)(h + (size_t)s1 * HID + li * 8);
#pragma unroll
        for (int q = 0; q < 4; q++) {
            float2 f0 = __half22float2(*(const __half2*)(&r0.x + q));
            float2 f1 = __half22float2(*(const __half2*)(&r1.x + q));
            acc[2 * q]     += f0.x + f1.x;
            acc[2 * q + 1] += f0.y + f1.y;
        }
    }
    if (j < e) {
        int s0 = __ldg(src + j);
        uint4 r0 = *(const uint4*)(h + (size_t)s0 * HID + li * 8);
#pragma unroll
        for (int q = 0; q < 4; q++) {
            float2 f0 = __half22float2(*(const __half2*)(&r0.x + q));
            acc[2 * q]     += f0.x;
            acc[2 * q + 1] += f0.y;
        }
    }
#pragma unroll
    for (int k = 0; k < 8; k++)
        acc[k] += __shfl_xor_sync(0xffffffffu, acc[k], 16);

    if (half == 0) {
        float inv = 1.f / fmaxf((float)(e - b), 1.f);
        uint4 o;
        ((__half2*)&o)[0] = __floats2half2_rn(acc[0] * inv, acc[1] * inv);
        ((__half2*)&o)[1] = __floats2half2_rn(acc[2] * inv, acc[3] * inv);
        ((__half2*)&o)[2] = __floats2half2_rn(acc[4] * inv, acc[5] * inv);
        ((__half2*)&o)[3] = __floats2half2_rn(acc[6] * inv, acc[7] * inv);
        *(uint4*)(outh + (size_t)node * HID + li * 8) = o;
    }
}

// ---------------- layer 1 fused: gather-mean(d=8) + GEMM + norm + tanh ----------------
__global__ void layer1_fused(const float* __restrict__ x,
                             const int* __restrict__ rp, const int* __restrict__ src,
                             const float* __restrict__ wl, const float* __restrict__ wr,
                             const float* __restrict__ bias,
                             __half* __restrict__ outh, int n) {
    __shared__ float s_wl[IN_DIM * HID];
    __shared__ float s_wr[IN_DIM * HID];
    __shared__ float s_b[HID];
    for (int i = threadIdx.x; i < IN_DIM * HID; i += blockDim.x) {
        s_wl[i] = wl[i];
        s_wr[i] = wr[i];
    }
    if (threadIdx.x < HID) s_b[threadIdx.x] = bias[threadIdx.x];
    __syncthreads();

    int warp = threadIdx.x >> 5, lane = threadIdx.x & 31;
    int node = blockIdx.x * (blockDim.x >> 5) + warp;
    if (node >= n) return;
    int grp = lane >> 3, dim = lane & 7;

    int b = __ldg(rp + node), e = __ldg(rp + node + 1);
    float acc8 = 0.f;
    for (int j = b + grp; j < e; j += 4) {
        int s0 = __ldg(src + j);
        acc8 += __ldg(x + (size_t)s0 * IN_DIM + dim);
    }
    acc8 += __shfl_xor_sync(0xffffffffu, acc8, 8);
    acc8 += __shfl_xor_sync(0xffffffffu, acc8, 16);
    acc8 *= 1.f / fmaxf((float)(e - b), 1.f);

    float my_x = __ldg(x + (size_t)node * IN_DIM + dim);

    float xs[8], as[8];
#pragma unroll
    for (int k = 0; k < 8; k++) {
        xs[k] = __shfl_sync(0xffffffffu, my_x, k);
        as[k] = __shfl_sync(0xffffffffu, acc8, k);
    }
    float acc[4];
#pragma unroll
    for (int c = 0; c < 4; c++) {
        int j = lane + 32 * c;
        float a = s_b[j];
#pragma unroll
        for (int k = 0; k < 8; k++)
            a += as[k] * s_wl[k * HID + j] + xs[k] * s_wr[k * HID + j];
        acc[c] = a;
    }
    float ss = acc[0] * acc[0] + acc[1] * acc[1] + acc[2] * acc[2] + acc[3] * acc[3];
#pragma unroll
    for (int o = 16; o >= 1; o >>= 1) ss += __shfl_xor_sync(0xffffffffu, ss, o);
    float invn = 1.f / fmaxf(sqrtf(ss), 1e-12f);
#pragma unroll
    for (int c = 0; c < 4; c++) {
        float v = tanhf(acc[c] * invn);
        outh[(size_t)node * HID + lane + 32 * c] = __float2half(v);
    }
}

// ---------------- fp16 tensor-core GEMM with ldmatrix, layers 2/3 ----------------
// A exact fp16; B = Bh + Bl fp16 split (err ~2^-22). 2 MMAs per tile.
#define BM 128
#define LDH 40   // smem row stride in halves (80B; 5*16B -> conflict-free LDSM)

__device__ __forceinline__ uint32_t smem_u32(const void* p) {
    return (uint32_t)__cvta_generic_to_shared(p);
}
__device__ __forceinline__ void ldsm_x4(uint32_t* r, uint32_t addr) {
    asm volatile("ldmatrix.sync.aligned.m8n8.x4.shared.b16 {%0,%1,%2,%3}, [%4];"
                 : "=r"(r[0]), "=r"(r[1]), "=r"(r[2]), "=r"(r[3]) : "r"(addr));
}
__device__ __forceinline__ void mma_f16(float* c, const uint32_t* a,
                                        uint32_t b0, uint32_t b1) {
    asm volatile(
        "mma.sync.aligned.m16n8k16.row.col.f32.f16.f16.f32 "
        "{%0,%1,%2,%3}, {%4,%5,%6,%7}, {%8,%9}, {%0,%1,%2,%3};"
        : "+f"(c[0]), "+f"(c[1]), "+f"(c[2]), "+f"(c[3])
        : "r"(a[0]), "r"(a[1]), "r"(a[2]), "r"(a[3]), "r"(b0), "r"(b1));
}

__global__ __launch_bounds__(256, 2) void layer23_tc(
    const __half* __restrict__ hinh, const __half* __restrict__ meanh,
    const __half* __restrict__ wth, const __half* __restrict__ wtl,
    const float* __restrict__ bias, float* __restrict__ out,
    __half* __restrict__ outh, int n) {
    __shared__ __half As[128 * LDH];
    __shared__ __half Bhs[128 * LDH];
    __shared__ __half Bls[128 * LDH];
    __shared__ float ss_part[2 * BM];

    int t = threadIdx.x;
    int row0 = blockIdx.x * BM;
    int wid = t >> 5, lane = t & 31;
    int warp_m = wid & 3;
    int warp_n = wid >> 2;
    int g = lane >> 2, tig = lane & 3;

    // staging ids: 2 threads per row, 16 halves (32B) each
    int m_st = t >> 1, part = t & 1;

    // ldmatrix lane bases (byte offsets into row-major [row][LDH] halves)
    uint32_t a_base = smem_u32(As) +
        ((warp_m * 32 + (lane & 15)) * LDH + (lane >> 4) * 8) * 2;
    uint32_t bh_base = smem_u32(Bhs) +
        ((warp_n * 64 + (lane & 15)) * LDH + (lane >> 4) * 8) * 2;
    uint32_t bl_base = smem_u32(Bls) +
        ((warp_n * 64 + (lane & 15)) * LDH + (lane >> 4) * 8) * 2;
    const uint32_t R16 = 16 * LDH * 2;  // 16 rows in bytes

    float acc[2][8][4];
#pragma unroll
    for (int i = 0; i < 2; i++)
#pragma unroll
        for (int j = 0; j < 8; j++)
#pragma unroll
            for (int c = 0; c < 4; c++) acc[i][j][c] = 0.f;

    for (int c = 0; c < 8; c++) {
        const __half* abase = (c < 4) ? meanh : hinh;
        int koff = (c & 3) * 32;
        // ---- stage A (fp16 copy) + B hi/lo (fp16 copy) ----
        {
            int gi = row0 + m_st;
            int ic = gi < n ? gi : n - 1;
            const uint4* asrc = (const uint4*)(abase + (size_t)ic * HID + koff + part * 16);
            uint4 a0 = asrc[0], a1 = asrc[1];
            __half* ad = As + m_st * LDH + part * 16;
            *(uint4*)ad = a0;
            *(uint4*)(ad + 8) = a1;

            const uint4* bhsrc = (const uint4*)(wth + m_st * 256 + c * 32 + part * 16);
            const uint4* blsrc = (const uint4*)(wtl + m_st * 256 + c * 32 + part * 16);
            uint4 bh0 = bhsrc[0], bh1 = bhsrc[1];
            uint4 bl0 = blsrc[0], bl1 = blsrc[1];
            __half* bhd = Bhs + m_st * LDH + part * 16;
            *(uint4*)bhd = bh0;
            *(uint4*)(bhd + 8) = bh1;
            __half* bld = Bls + m_st * LDH + part * 16;
            *(uint4*)bld = bl0;
            *(uint4*)(bld + 8) = bl1;
        }
        __syncthreads();

#pragma unroll
        for (int s = 0; s < 2; s++) {
            uint32_t a[2][4];
            ldsm_x4(a[0], a_base + s * 32);
            ldsm_x4(a[1], a_base + s * 32 + R16);
#pragma unroll
            for (int p = 0; p < 4; p++) {
                uint32_t bh[4], bl[4];
                ldsm_x4(bh, bh_base + p * R16 + s * 32);
                ldsm_x4(bl, bl_base + p * R16 + s * 32);
#pragma unroll
                for (int mi = 0; mi < 2; mi++) {
                    mma_f16(acc[mi][2 * p],     a[mi], bh[0], bh[2]);
                    mma_f16(acc[mi][2 * p],     a[mi], bl[0], bl[2]);
                    mma_f16(acc[mi][2 * p + 1], a[mi], bh[1], bh[3]);
                    mma_f16(acc[mi][2 * p + 1], a[mi], bl[1], bl[3]);
                }
            }
        }
        __syncthreads();
    }

    // ---- epilogue: +bias, row L2 norm across 128 cols, tanh ----
    float2 bv[8];
#pragma unroll
    for (int nt = 0; nt < 8; nt++)
        bv[nt] = *(const float2*)(bias + warp_n * 64 + nt * 8 + 2 * tig);

#pragma unroll
    for (int mi = 0; mi < 2; mi++) {
#pragma unroll
        for (int h = 0; h < 2; h++) {
            float ss = 0.f;
#pragma unroll
            for (int nt = 0; nt < 8; nt++) {
                acc[mi][nt][2 * h]     += bv[nt].x;
                acc[mi][nt][2 * h + 1] += bv[nt].y;
                ss += acc[mi][nt][2 * h] * acc[mi][nt][2 * h]
                    + acc[mi][nt][2 * h + 1] * acc[mi][nt][2 * h + 1];
            }
            ss += __shfl_xor_sync(0xffffffffu, ss, 1);
            ss += __shfl_xor_sync(0xffffffffu, ss, 2);
            if (tig == 0)
                ss_part[warp_n * BM + warp_m * 32 + mi * 16 + h * 8 + g] = ss;
        }
    }
    __syncthreads();

#pragma unroll
    for (int mi = 0; mi < 2; mi++) {
#pragma unroll
        for (int h = 0; h < 2; h++) {
            int rloc = warp_m * 32 + mi * 16 + h * 8 + g;
            int gi = row0 + rloc;
            if (gi >= n) continue;
            float tot = ss_part[rloc] + ss_part[BM + rloc];
            float invn = 1.f / fmaxf(sqrtf(tot), 1e-12f);
#pragma unroll
            for (int nt = 0; nt < 8; nt++) {
                float2 o;
                o.x = tanhf(acc[mi][nt][2 * h] * invn);
                o.y = tanhf(acc[mi][nt][2 * h + 1] * invn);
                size_t off = (size_t)gi * HID + warp_n * 64 + nt * 8 + 2 * tig;
                if (out) *(float2*)(out + off) = o;
                if (outh) *(__half2*)(outh + off) = __floats2half2_rn(o.x, o.y);
            }
        }
    }
}

// ---------------- launch ----------------
extern "C" void kernel_launch(void* const* d_in, const int* in_sizes, int n_in,
                              void* d_out, int out_size) {
    const float* x       = (const float*)d_in[0];
    const int*   ei_conn = (const int*)d_in[1];
    const int*   ei_dest = (const int*)d_in[2];
    const float* w_l1 = (const float*)d_in[3];
    const float* w_r1 = (const float*)d_in[4];
    const float* b1   = (const float*)d_in[5];
    const float* w_l2 = (const float*)d_in[6];
    const float* w_r2 = (const float*)d_in[7];
    const float* b2   = (const float*)d_in[8];
    const float* w_l3 = (const float*)d_in[9];
    const float* w_r3 = (const float*)d_in[10];
    const float* b3   = (const float*)d_in[11];
    float* out = (float*)d_out;

    const int n = N_NODES;
    const int E = in_sizes[1] / 2;

    __half *p_h1h, *p_h2h, *p_aggh, *p_w2h, *p_w2l, *p_w3h, *p_w3l;
    int *p_cnt_c, *p_cnt_d, *p_rp_c, *p_rp_d, *p_cur_c, *p_cur_d, *p_src_c, *p_src_d;
    cudaGetSymbolAddress((void**)&p_h1h, g_h1h);
    cudaGetSymbolAddress((void**)&p_h2h, g_h2h);
    cudaGetSymbolAddress((void**)&p_aggh, g_aggh);
    cudaGetSymbolAddress((void**)&p_w2h, g_wt2h);
    cudaGetSymbolAddress((void**)&p_w2l, g_wt2l);
    cudaGetSymbolAddress((void**)&p_w3h, g_wt3h);
    cudaGetSymbolAddress((void**)&p_w3l, g_wt3l);
    cudaGetSymbolAddress((void**)&p_cnt_c, g_cnt_c);
    cudaGetSymbolAddress((void**)&p_cnt_d, g_cnt_d);
    cudaGetSymbolAddress((void**)&p_rp_c, g_rp_c);
    cudaGetSymbolAddress((void**)&p_rp_d, g_rp_d);
    cudaGetSymbolAddress((void**)&p_cur_c, g_cur_c);
    cudaGetSymbolAddress((void**)&p_cur_d, g_cur_d);
    cudaGetSymbolAddress((void**)&p_src_c, g_src_c);
    cudaGetSymbolAddress((void**)&p_src_d, g_src_d);

    static cudaStream_t sB = nullptr;
    static cudaEvent_t evFork = nullptr, evJoin = nullptr;
    if (!sB) {
        cudaStreamCreateWithFlags(&sB, cudaStreamNonBlocking);
        cudaEventCreateWithFlags(&evFork, cudaEventDisableTiming);
        cudaEventCreateWithFlags(&evJoin, cudaEventDisableTiming);
    }

    // ---- fork: weight prep + dest-list CSR on side stream ----
    cudaEventRecord(evFork, 0);
    cudaStreamWaitEvent(sB, evFork, 0);
    wprep<<<(2 * 128 * 256 + 255) / 256, 256, 0, sB>>>(w_l2, w_r2, w_l3, w_r3,
                                                       p_w2h, p_w2l, p_w3h, p_w3l);
    zero1<<<(n + 255) / 256, 256, 0, sB>>>(p_cnt_d, n);
    hist1<<<1024, 256, 0, sB>>>(ei_dest, E, p_cnt_d);
    scan1<<<1, 1024, 0, sB>>>(p_cnt_d, p_rp_d, p_cur_d, n);
    fill1<<<1024, 256, 0, sB>>>(ei_dest, E, p_cur_d, p_src_d);
    cudaEventRecord(evJoin, sB);

    // ---- main stream: conn-list CSR + layer 1 ----
    zero1<<<(n + 255) / 256, 256>>>(p_cnt_c, n);
    hist1<<<1024, 256>>>(ei_conn, E, p_cnt_c);
    scan1<<<1, 1024>>>(p_cnt_c, p_rp_c, p_cur_c, n);
    fill1<<<1024, 256>>>(ei_conn, E, p_cur_c, p_src_c);
    layer1_fused<<<(n + 7) / 8, 256>>>(x, p_rp_c, p_src_c, w_l1, w_r1, b1, p_h1h, n);

    // ---- join, then layer 2 (dest) ----
    cudaStreamWaitEvent(0, evJoin, 0);
    gather128h<<<(n * 32 + 255) / 256, 256>>>(p_h1h, p_rp_d, p_src_d, p_aggh, n);
    layer23_tc<<<(n + BM - 1) / BM, 256>>>(p_h1h, p_aggh, p_w2h, p_w2l, b2,
                                           nullptr, p_h2h, n);

    // ---- layer 3 (conn) ----
    gather128h<<<(n * 32 + 255) / 256, 256>>>(p_h2h, p_rp_c, p_src_c, p_aggh, n);
    layer23_tc<<<(n + BM - 1) / BM, 256>>>(p_h2h, p_aggh, p_w3h, p_w3l, b3,
                                           out, nullptr, n);
}

// round 10
// speedup vs baseline: 2.4753x; 1.4104x over previous
#include <cuda_runtime.h>
#include <cuda_fp16.h>
#include <cstdint>

#define N_NODES 100000
#define N_EDGES 1600000
#define HID 128
#define IN_DIM 8
#define SCH 512                      // elements per scan block
#define SNB ((N_NODES + SCH - 1) / SCH)  // 196

// ---------------- scratch (static __device__, no allocation) ----------------
__device__ __half g_h1h[(size_t)N_NODES * HID];
__device__ __half g_h2h[(size_t)N_NODES * HID];
__device__ __half g_aggh[(size_t)N_NODES * HID];
__device__ __half g_wt2h[128 * 256];
__device__ __half g_wt2l[128 * 256];
__device__ __half g_wt3h[128 * 256];
__device__ __half g_wt3l[128 * 256];
__device__ int g_cnt_c[N_NODES];
__device__ int g_cnt_d[N_NODES];
__device__ int g_rp_c[N_NODES + 1];
__device__ int g_rp_d[N_NODES + 1];
__device__ int g_cur_c[N_NODES];
__device__ int g_cur_d[N_NODES];
__device__ int g_src_c[N_EDGES];
__device__ int g_src_d[N_EDGES];
__device__ int g_bsum_c[SNB];
__device__ int g_bsum_d[SNB];
__device__ int g_boff_c[SNB];
__device__ int g_boff_d[SNB];

// ---------------- CSR build (per-list) ----------------
__global__ void zero1(int* a, int n) {
    int i = blockIdx.x * blockDim.x + threadIdx.x;
    int st = gridDim.x * blockDim.x;
    for (; i < n; i += st) a[i] = 0;
}
__global__ void hist1(const int* __restrict__ ei, int E, int* cnt) {
    int i = blockIdx.x * blockDim.x + threadIdx.x;
    int st = gridDim.x * blockDim.x;
    for (; i < E; i += st) atomicAdd(&cnt[ei[E + i]], 1);
}

// pass 1: per-block sum of 512 counts
__global__ __launch_bounds__(256) void scan_p1(const int* __restrict__ cnt,
                                               int* __restrict__ bsum, int n) {
    __shared__ int s[8];
    int b = blockIdx.x, t = threadIdx.x;
    int i0 = b * SCH + t;
    int v = 0;
    if (i0 < n) v += cnt[i0];
    if (i0 + 256 < n) v += cnt[i0 + 256];
#pragma unroll
    for (int o = 16; o >= 1; o >>= 1) v += __shfl_xor_sync(0xffffffffu, v, o);
    if ((t & 31) == 0) s[t >> 5] = v;
    __syncthreads();
    if (t < 8) {
        int w = s[t];
#pragma unroll
        for (int o = 4; o >= 1; o >>= 1) w += __shfl_xor_sync(0xffu, w, o);
        if (t == 0) bsum[b] = w;
    }
}

// pass 2: exclusive scan of block sums (SNB <= 256), writes rp[n]=total
__global__ __launch_bounds__(256) void scan_p2(const int* __restrict__ bsum,
                                               int* __restrict__ boff,
                                               int* __restrict__ rp, int nb, int n) {
    __shared__ int s[256];
    int t = threadIdx.x;
    int v = (t < nb) ? bsum[t] : 0;
    s[t] = v;
    __syncthreads();
#pragma unroll
    for (int o = 1; o < 256; o <<= 1) {
        int u = (t >= o) ? s[t - o] : 0;
        __syncthreads();
        s[t] += u;
        __syncthreads();
    }
    if (t < nb) boff[t] = s[t] - v;  // exclusive
    if (t == 255) rp[n] = s[255];
}

// pass 3: block-local exclusive scan (2 elems/thread) + boff, write rp & cur
__global__ __launch_bounds__(256) void scan_p3(const int* __restrict__ cnt,
                                               const int* __restrict__ boff,
                                               int* __restrict__ rp,
                                               int* __restrict__ cur, int n) {
    __shared__ int wsum[8];
    int b = blockIdx.x, t = threadIdx.x;
    int lane = t & 31, wrp = t >> 5;
    int i0 = b * SCH + 2 * t;
    int c0 = (i0 < n) ? cnt[i0] : 0;
    int c1 = (i0 + 1 < n) ? cnt[i0 + 1] : 0;
    int ps = c0 + c1;
    int x = ps;
#pragma unroll
    for (int o = 1; o < 32; o <<= 1) {
        int u = __shfl_up_sync(0xffffffffu, x, o);
        if (lane >= o) x += u;
    }
    if (lane == 31) wsum[wrp] = x;
    __syncthreads();
    int woff = 0;
    if (t < 8) {
        int w = wsum[t];
        int y = w;
#pragma unroll
        for (int o = 1; o < 8; o <<= 1) {
            int u = __shfl_up_sync(0xffu, y, o);
            if (t >= o) y += u;
        }
        wsum[t] = y - w;  // exclusive warp offsets
    }
    __syncthreads();
    woff = wsum[wrp];
    int pre = boff[b] + woff + (x - ps);  // exclusive prefix for i0
    if (i0 < n) { rp[i0] = pre; cur[i0] = pre; }
    if (i0 + 1 < n) { rp[i0 + 1] = pre + c0; cur[i0 + 1] = pre + c0; }
}

__global__ void fill1(const int* __restrict__ ei, int E, int* cur,
                      int* __restrict__ srcl) {
    int i = blockIdx.x * blockDim.x + threadIdx.x;
    int st = gridDim.x * blockDim.x;
    for (; i < E; i += st) {
        int s = ei[i], d = ei[E + i];
        srcl[atomicAdd(&cur[d], 1)] = s;
    }
}

// ---------------- weight prep: W[k][n] fp32 -> Wt[n][256] fp16 hi/lo ----------------
__global__ void wprep(const float* __restrict__ wl2, const float* __restrict__ wr2,
                      const float* __restrict__ wl3, const float* __restrict__ wr3,
                      __half* w2h, __half* w2l, __half* w3h, __half* w3l) {
    int i = blockIdx.x * blockDim.x + threadIdx.x;
    if (i >= 2 * 128 * 256) return;
    int layer = i >> 15;
    int rem = i & 32767;
    int nrow = rem >> 8, k = rem & 255;
    const float* wlm = layer ? wl3 : wl2;
    const float* wrm = layer ? wr3 : wr2;
    float v = (k < 128) ? wlm[k * 128 + nrow] : wrm[(k - 128) * 128 + nrow];
    __half h = __float2half(v);
    __half l = __float2half(v - __half2float(h));
    (layer ? w3h : w2h)[nrow * 256 + k] = h;
    (layer ? w3l : w2l)[nrow * 256 + k] = l;
}

// ---------------- gather-mean over fp16 rows -> fp16 mean, d=128 ----------------
__global__ void gather128h(const __half* __restrict__ h, const int* __restrict__ rp,
                           const int* __restrict__ src, __half* __restrict__ outh, int n) {
    int node = (blockIdx.x * blockDim.x + threadIdx.x) >> 5;
    int lane = threadIdx.x & 31;
    if (node >= n) return;
    int half = lane >> 4, li = lane & 15;
    int b = __ldg(rp + node), e = __ldg(rp + node + 1);
    float acc[8];
#pragma unroll
    for (int k = 0; k < 8; k++) acc[k] = 0.f;

    int j = b + half;
    for (; j + 2 < e; j += 4) {
        int s0 = __ldg(src + j);
        int s1 = __ldg(src + j + 2);
        uint4 r0 = *(const uint4*)(h + (size_t)s0 * HID + li * 8);
        uint4 r1 = *(const uint4*)(h + (size_t)s1 * HID + li * 8);
#pragma unroll
        for (int q = 0; q < 4; q++) {
            float2 f0 = __half22float2(*(const __half2*)(&r0.x + q));
            float2 f1 = __half22float2(*(const __half2*)(&r1.x + q));
            acc[2 * q]     += f0.x + f1.x;
            acc[2 * q + 1] += f0.y + f1.y;
        }
    }
    if (j < e) {
        int s0 = __ldg(src + j);
        uint4 r0 = *(const uint4*)(h + (size_t)s0 * HID + li * 8);
#pragma unroll
        for (int q = 0; q < 4; q++) {
            float2 f0 = __half22float2(*(const __half2*)(&r0.x + q));
            acc[2 * q]     += f0.x;
            acc[2 * q + 1] += f0.y;
        }
    }
#pragma unroll
    for (int k = 0; k < 8; k++)
        acc[k] += __shfl_xor_sync(0xffffffffu, acc[k], 16);

    if (half == 0) {
        float inv = 1.f / fmaxf((float)(e - b), 1.f);
        uint4 o;
        ((__half2*)&o)[0] = __floats2half2_rn(acc[0] * inv, acc[1] * inv);
        ((__half2*)&o)[1] = __floats2half2_rn(acc[2] * inv, acc[3] * inv);
        ((__half2*)&o)[2] = __floats2half2_rn(acc[4] * inv, acc[5] * inv);
        ((__half2*)&o)[3] = __floats2half2_rn(acc[6] * inv, acc[7] * inv);
        *(uint4*)(outh + (size_t)node * HID + li * 8) = o;
    }
}

// ---------------- layer 1 fused: gather-mean(d=8) + GEMM + norm + tanh ----------------
__global__ void layer1_fused(const float* __restrict__ x,
                             const int* __restrict__ rp, const int* __restrict__ src,
                             const float* __restrict__ wl, const float* __restrict__ wr,
                             const float* __restrict__ bias,
                             __half* __restrict__ outh, int n) {
    __shared__ float s_wl[IN_DIM * HID];
    __shared__ float s_wr[IN_DIM * HID];
    __shared__ float s_b[HID];
    for (int i = threadIdx.x; i < IN_DIM * HID; i += blockDim.x) {
        s_wl[i] = wl[i];
        s_wr[i] = wr[i];
    }
    if (threadIdx.x < HID) s_b[threadIdx.x] = bias[threadIdx.x];
    __syncthreads();

    int warp = threadIdx.x >> 5, lane = threadIdx.x & 31;
    int node = blockIdx.x * (blockDim.x >> 5) + warp;
    if (node >= n) return;
    int grp = lane >> 3, dim = lane & 7;

    int b = __ldg(rp + node), e = __ldg(rp + node + 1);
    float acc8 = 0.f;
    for (int j = b + grp; j < e; j += 4) {
        int s0 = __ldg(src + j);
        acc8 += __ldg(x + (size_t)s0 * IN_DIM + dim);
    }
    acc8 += __shfl_xor_sync(0xffffffffu, acc8, 8);
    acc8 += __shfl_xor_sync(0xffffffffu, acc8, 16);
    acc8 *= 1.f / fmaxf((float)(e - b), 1.f);

    float my_x = __ldg(x + (size_t)node * IN_DIM + dim);

    float xs[8], as[8];
#pragma unroll
    for (int k = 0; k < 8; k++) {
        xs[k] = __shfl_sync(0xffffffffu, my_x, k);
        as[k] = __shfl_sync(0xffffffffu, acc8, k);
    }
    float acc[4];
#pragma unroll
    for (int c = 0; c < 4; c++) {
        int j = lane + 32 * c;
        float a = s_b[j];
#pragma unroll
        for (int k = 0; k < 8; k++)
            a += as[k] * s_wl[k * HID + j] + xs[k] * s_wr[k * HID + j];
        acc[c] = a;
    }
    float ss = acc[0] * acc[0] + acc[1] * acc[1] + acc[2] * acc[2] + acc[3] * acc[3];
#pragma unroll
    for (int o = 16; o >= 1; o >>= 1) ss += __shfl_xor_sync(0xffffffffu, ss, o);
    float invn = 1.f / fmaxf(sqrtf(ss), 1e-12f);
#pragma unroll
    for (int c = 0; c < 4; c++) {
        float v = tanhf(acc[c] * invn);
        outh[(size_t)node * HID + lane + 32 * c] = __float2half(v);
    }
}

// ---------------- fp16 tensor-core GEMM with ldmatrix, layers 2/3 ----------------
#define BM 128
#define LDH 40

__device__ __forceinline__ uint32_t smem_u32(const void* p) {
    return (uint32_t)__cvta_generic_to_shared(p);
}
__device__ __forceinline__ void ldsm_x4(uint32_t* r, uint32_t addr) {
    asm volatile("ldmatrix.sync.aligned.m8n8.x4.shared.b16 {%0,%1,%2,%3}, [%4];"
                 : "=r"(r[0]), "=r"(r[1]), "=r"(r[2]), "=r"(r[3]) : "r"(addr));
}
__device__ __forceinline__ void mma_f16(float* c, const uint32_t* a,
                                        uint32_t b0, uint32_t b1) {
    asm volatile(
        "mma.sync.aligned.m16n8k16.row.col.f32.f16.f16.f32 "
        "{%0,%1,%2,%3}, {%4,%5,%6,%7}, {%8,%9}, {%0,%1,%2,%3};"
        : "+f"(c[0]), "+f"(c[1]), "+f"(c[2]), "+f"(c[3])
        : "r"(a[0]), "r"(a[1]), "r"(a[2]), "r"(a[3]), "r"(b0), "r"(b1));
}

__global__ __launch_bounds__(256, 2) void layer23_tc(
    const __half* __restrict__ hinh, const __half* __restrict__ meanh,
    const __half* __restrict__ wth, const __half* __restrict__ wtl,
    const float* __restrict__ bias, float* __restrict__ out,
    __half* __restrict__ outh, int n) {
    __shared__ __half As[128 * LDH];
    __shared__ __half Bhs[128 * LDH];
    __shared__ __half Bls[128 * LDH];
    __shared__ float ss_part[2 * BM];

    int t = threadIdx.x;
    int row0 = blockIdx.x * BM;
    int wid = t >> 5, lane = t & 31;
    int warp_m = wid & 3;
    int warp_n = wid >> 2;
    int g = lane >> 2, tig = lane & 3;

    int m_st = t >> 1, part = t & 1;

    uint32_t a_base = smem_u32(As) +
        ((warp_m * 32 + (lane & 15)) * LDH + (lane >> 4) * 8) * 2;
    uint32_t bh_base = smem_u32(Bhs) +
        ((warp_n * 64 + (lane & 15)) * LDH + (lane >> 4) * 8) * 2;
    uint32_t bl_base = smem_u32(Bls) +
        ((warp_n * 64 + (lane & 15)) * LDH + (lane >> 4) * 8) * 2;
    const uint32_t R16 = 16 * LDH * 2;

    float acc[2][8][4];
#pragma unroll
    for (int i = 0; i < 2; i++)
#pragma unroll
        for (int j = 0; j < 8; j++)
#pragma unroll
            for (int c = 0; c < 4; c++) acc[i][j][c] = 0.f;

    for (int c = 0; c < 8; c++) {
        const __half* abase = (c < 4) ? meanh : hinh;
        int koff = (c & 3) * 32;
        {
            int gi = row0 + m_st;
            int ic = gi < n ? gi : n - 1;
            const uint4* asrc = (const uint4*)(abase + (size_t)ic * HID + koff + part * 16);
            uint4 a0 = asrc[0], a1 = asrc[1];
            __half* ad = As + m_st * LDH + part * 16;
            *(uint4*)ad = a0;
            *(uint4*)(ad + 8) = a1;

            const uint4* bhsrc = (const uint4*)(wth + m_st * 256 + c * 32 + part * 16);
            const uint4* blsrc = (const uint4*)(wtl + m_st * 256 + c * 32 + part * 16);
            uint4 bh0 = bhsrc[0], bh1 = bhsrc[1];
            uint4 bl0 = blsrc[0], bl1 = blsrc[1];
            __half* bhd = Bhs + m_st * LDH + part * 16;
            *(uint4*)bhd = bh0;
            *(uint4*)(bhd + 8) = bh1;
            __half* bld = Bls + m_st * LDH + part * 16;
            *(uint4*)bld = bl0;
            *(uint4*)(bld + 8) = bl1;
        }
        __syncthreads();

#pragma unroll
        for (int s = 0; s < 2; s++) {
            uint32_t a[2][4];
            ldsm_x4(a[0], a_base + s * 32);
            ldsm_x4(a[1], a_base + s * 32 + R16);
#pragma unroll
            for (int p = 0; p < 4; p++) {
                uint32_t bh[4], bl[4];
                ldsm_x4(bh, bh_base + p * R16 + s * 32);
                ldsm_x4(bl, bl_base + p * R16 + s * 32);
#pragma unroll
                for (int mi = 0; mi < 2; mi++) {
                    mma_f16(acc[mi][2 * p],     a[mi], bh[0], bh[2]);
                    mma_f16(acc[mi][2 * p],     a[mi], bl[0], bl[2]);
                    mma_f16(acc[mi][2 * p + 1], a[mi], bh[1], bh[3]);
                    mma_f16(acc[mi][2 * p + 1], a[mi], bl[1], bl[3]);
                }
            }
        }
        __syncthreads();
    }

    float2 bv[8];
#pragma unroll
    for (int nt = 0; nt < 8; nt++)
        bv[nt] = *(const float2*)(bias + warp_n * 64 + nt * 8 + 2 * tig);

#pragma unroll
    for (int mi = 0; mi < 2; mi++) {
#pragma unroll
        for (int h = 0; h < 2; h++) {
            float ss = 0.f;
#pragma unroll
            for (int nt = 0; nt < 8; nt++) {
                acc[mi][nt][2 * h]     += bv[nt].x;
                acc[mi][nt][2 * h + 1] += bv[nt].y;
                ss += acc[mi][nt][2 * h] * acc[mi][nt][2 * h]
                    + acc[mi][nt][2 * h + 1] * acc[mi][nt][2 * h + 1];
            }
            ss += __shfl_xor_sync(0xffffffffu, ss, 1);
            ss += __shfl_xor_sync(0xffffffffu, ss, 2);
            if (tig == 0)
                ss_part[warp_n * BM + warp_m * 32 + mi * 16 + h * 8 + g] = ss;
        }
    }
    __syncthreads();

#pragma unroll
    for (int mi = 0; mi < 2; mi++) {
#pragma unroll
        for (int h = 0; h < 2; h++) {
            int rloc = warp_m * 32 + mi * 16 + h * 8 + g;
            int gi = row0 + rloc;
            if (gi >= n) continue;
            float tot = ss_part[rloc] + ss_part[BM + rloc];
            float invn = 1.f / fmaxf(sqrtf(tot), 1e-12f);
#pragma unroll
            for (int nt = 0; nt < 8; nt++) {
                float2 o;
                o.x = tanhf(acc[mi][nt][2 * h] * invn);
                o.y = tanhf(acc[mi][nt][2 * h + 1] * invn);
                size_t off = (size_t)gi * HID + warp_n * 64 + nt * 8 + 2 * tig;
                if (out) *(float2*)(out + off) = o;
                if (outh) *(__half2*)(outh + off) = __floats2half2_rn(o.x, o.y);
            }
        }
    }
}

// ---------------- launch ----------------
extern "C" void kernel_launch(void* const* d_in, const int* in_sizes, int n_in,
                              void* d_out, int out_size) {
    const float* x       = (const float*)d_in[0];
    const int*   ei_conn = (const int*)d_in[1];
    const int*   ei_dest = (const int*)d_in[2];
    const float* w_l1 = (const float*)d_in[3];
    const float* w_r1 = (const float*)d_in[4];
    const float* b1   = (const float*)d_in[5];
    const float* w_l2 = (const float*)d_in[6];
    const float* w_r2 = (const float*)d_in[7];
    const float* b2   = (const float*)d_in[8];
    const float* w_l3 = (const float*)d_in[9];
    const float* w_r3 = (const float*)d_in[10];
    const float* b3   = (const float*)d_in[11];
    float* out = (float*)d_out;

    const int n = N_NODES;
    const int E = in_sizes[1] / 2;

    __half *p_h1h, *p_h2h, *p_aggh, *p_w2h, *p_w2l, *p_w3h, *p_w3l;
    int *p_cnt_c, *p_cnt_d, *p_rp_c, *p_rp_d, *p_cur_c, *p_cur_d, *p_src_c, *p_src_d;
    int *p_bs_c, *p_bs_d, *p_bo_c, *p_bo_d;
    cudaGetSymbolAddress((void**)&p_h1h, g_h1h);
    cudaGetSymbolAddress((void**)&p_h2h, g_h2h);
    cudaGetSymbolAddress((void**)&p_aggh, g_aggh);
    cudaGetSymbolAddress((void**)&p_w2h, g_wt2h);
    cudaGetSymbolAddress((void**)&p_w2l, g_wt2l);
    cudaGetSymbolAddress((void**)&p_w3h, g_wt3h);
    cudaGetSymbolAddress((void**)&p_w3l, g_wt3l);
    cudaGetSymbolAddress((void**)&p_cnt_c, g_cnt_c);
    cudaGetSymbolAddress((void**)&p_cnt_d, g_cnt_d);
    cudaGetSymbolAddress((void**)&p_rp_c, g_rp_c);
    cudaGetSymbolAddress((void**)&p_rp_d, g_rp_d);
    cudaGetSymbolAddress((void**)&p_cur_c, g_cur_c);
    cudaGetSymbolAddress((void**)&p_cur_d, g_cur_d);
    cudaGetSymbolAddress((void**)&p_src_c, g_src_c);
    cudaGetSymbolAddress((void**)&p_src_d, g_src_d);
    cudaGetSymbolAddress((void**)&p_bs_c, g_bsum_c);
    cudaGetSymbolAddress((void**)&p_bs_d, g_bsum_d);
    cudaGetSymbolAddress((void**)&p_bo_c, g_boff_c);
    cudaGetSymbolAddress((void**)&p_bo_d, g_boff_d);

    static cudaStream_t sB = nullptr;
    static cudaEvent_t evFork = nullptr, evJoin = nullptr;
    if (!sB) {
        cudaStreamCreateWithFlags(&sB, cudaStreamNonBlocking);
        cudaEventCreateWithFlags(&evFork, cudaEventDisableTiming);
        cudaEventCreateWithFlags(&evJoin, cudaEventDisableTiming);
    }

    // ---- fork: weight prep + dest-list CSR on side stream ----
    cudaEventRecord(evFork, 0);
    cudaStreamWaitEvent(sB, evFork, 0);
    wprep<<<(2 * 128 * 256 + 255) / 256, 256, 0, sB>>>(w_l2, w_r2, w_l3, w_r3,
                                                       p_w2h, p_w2l, p_w3h, p_w3l);
    zero1<<<(n + 255) / 256, 256, 0, sB>>>(p_cnt_d, n);
    hist1<<<1024, 256, 0, sB>>>(ei_dest, E, p_cnt_d);
    scan_p1<<<SNB, 256, 0, sB>>>(p_cnt_d, p_bs_d, n);
    scan_p2<<<1, 256, 0, sB>>>(p_bs_d, p_bo_d, p_rp_d, SNB, n);
    scan_p3<<<SNB, 256, 0, sB>>>(p_cnt_d, p_bo_d, p_rp_d, p_cur_d, n);
    fill1<<<1024, 256, 0, sB>>>(ei_dest, E, p_cur_d, p_src_d);
    cudaEventRecord(evJoin, sB);

    // ---- main stream: conn-list CSR + layer 1 ----
    zero1<<<(n + 255) / 256, 256>>>(p_cnt_c, n);
    hist1<<<1024, 256>>>(ei_conn, E, p_cnt_c);
    scan_p1<<<SNB, 256>>>(p_cnt_c, p_bs_c, n);
    scan_p2<<<1, 256>>>(p_bs_c, p_bo_c, p_rp_c, SNB, n);
    scan_p3<<<SNB, 256>>>(p_cnt_c, p_bo_c, p_rp_c, p_cur_c, n);
    fill1<<<1024, 256>>>(ei_conn, E, p_cur_c, p_src_c);
    layer1_fused<<<(n + 7) / 8, 256>>>(x, p_rp_c, p_src_c, w_l1, w_r1, b1, p_h1h, n);

    // ---- join, then layer 2 (dest) ----
    cudaStreamWaitEvent(0, evJoin, 0);
    gather128h<<<(n * 32 + 255) / 256, 256>>>(p_h1h, p_rp_d, p_src_d, p_aggh, n);
    layer23_tc<<<(n + BM - 1) / BM, 256>>>(p_h1h, p_aggh, p_w2h, p_w2l, b2,
                                           nullptr, p_h2h, n);

    // ---- layer 3 (conn) ----
    gather128h<<<(n * 32 + 255) / 256, 256>>>(p_h2h, p_rp_c, p_src_c, p_aggh, n);
    layer23_tc<<<(n + BM - 1) / BM, 256>>>(p_h2h, p_aggh, p_w3h, p_w3l, b3,
                                           out, nullptr, n);
}